// round 3
// baseline (speedup 1.0000x reference)
#include <cuda_runtime.h>
#include <stdint.h>
#include <math.h>

#define N_MAX 100000
#define E_MAX 1600000
#define HD 128

// ---------------- device scratch (static; no allocations) ----------------
__device__ int   g_src[E_MAX];
__device__ int   g_dst[E_MAX];
__device__ int   g_deg[N_MAX];
__device__ int   g_rowStart[N_MAX + 1];
__device__ int   g_cursor[N_MAX];
__device__ float g_dinv[N_MAX];
__device__ int   g_csr_src[E_MAX];
__device__ float g_csr_norm[E_MAX];
__device__ float g_bufA[(size_t)N_MAX * HD];
__device__ float g_bufB[(size_t)N_MAX * HD];
__device__ int   g_zero_cnt;

// ---------------- preprocessing kernels ----------------

__global__ void zero_kernel(int n) {
    int i = blockIdx.x * blockDim.x + threadIdx.x;
    if (i < n) g_deg[i] = 0;
    if (i == 0) g_zero_cnt = 0;
}

// Detect int64 vs int32 edge_index: sample 65536 odd 32-bit words.
// int64 (values < 2^31): all high halves are 0 -> count = 65536.
// int32: words are uniform in [0,100000) -> expected ~0.65 zeros.
__global__ void detect_kernel(const unsigned int* __restrict__ ebuf) {
    int i = blockIdx.x * blockDim.x + threadIdx.x;  // 65536 threads
    int z = (ebuf[2 * i + 1] == 0u) ? 1 : 0;
    unsigned m = __ballot_sync(0xFFFFFFFFu, z);
    if ((threadIdx.x & 31) == 0) atomicAdd(&g_zero_cnt, __popc(m));
}

// Extract src/dst as int32 + histogram in-degree of dst.
__global__ void extract_kernel(const unsigned int* __restrict__ ebuf, int e) {
    bool is64 = (g_zero_cnt > 1000);
    for (int i = blockIdx.x * blockDim.x + threadIdx.x; i < e;
         i += gridDim.x * blockDim.x) {
        int s, d;
        if (is64) {
            s = (int)ebuf[2 * (size_t)i];
            d = (int)ebuf[2 * ((size_t)e + i)];
        } else {
            s = (int)ebuf[i];
            d = (int)ebuf[e + i];
        }
        g_src[i] = s;
        g_dst[i] = d;
        atomicAdd(&g_deg[d], 1);
    }
}

__global__ void dinv_kernel(int n) {
    int i = blockIdx.x * blockDim.x + threadIdx.x;
    if (i < n) g_dinv[i] = rsqrtf((float)(g_deg[i] + 1));  // +1 self-loop
}

// Single-block exclusive scan of g_deg -> g_rowStart (+ cursor copy).
__global__ void scan_kernel(int n) {
    __shared__ int warp_pref[32];
    __shared__ int carry_s;
    int tid = threadIdx.x, lane = tid & 31, wid = tid >> 5;
    if (tid == 0) carry_s = 0;
    __syncthreads();
    for (int base = 0; base < n; base += 1024) {
        int i = base + tid;
        int v = (i < n) ? g_deg[i] : 0;
        int incl = v;
#pragma unroll
        for (int o = 1; o < 32; o <<= 1) {
            int t = __shfl_up_sync(0xFFFFFFFFu, incl, o);
            if (lane >= o) incl += t;
        }
        if (lane == 31) warp_pref[wid] = incl;
        __syncthreads();
        if (wid == 0) {
            int s = warp_pref[lane];
#pragma unroll
            for (int o = 1; o < 32; o <<= 1) {
                int t = __shfl_up_sync(0xFFFFFFFFu, s, o);
                if (lane >= o) s += t;
            }
            warp_pref[lane] = s;
        }
        __syncthreads();
        int off = carry_s + (wid ? warp_pref[wid - 1] : 0);
        int excl = off + incl - v;
        if (i < n) {
            g_rowStart[i] = excl;
            g_cursor[i] = excl;
        }
        __syncthreads();
        if (tid == 0) carry_s += warp_pref[31];
        __syncthreads();
    }
    if (threadIdx.x == 0) g_rowStart[n] = carry_s;
}

__global__ void fill_kernel(int e) {
    for (int i = blockIdx.x * blockDim.x + threadIdx.x; i < e;
         i += gridDim.x * blockDim.x) {
        int d = g_dst[i];
        int s = g_src[i];
        int pos = atomicAdd(&g_cursor[d], 1);
        g_csr_src[pos] = s;
        g_csr_norm[pos] = g_dinv[s] * g_dinv[d];
    }
}

// ---------------- SGEMM: C[M,128] = A[M,128] @ W[128,128] ----------------
// 128x128 block tile, 8x8 thread tile, BK=8, double-buffered smem.

__global__ __launch_bounds__(256, 2)
void gemm128_kernel(const float* __restrict__ A, const float* __restrict__ W,
                    float* __restrict__ C, int M) {
    __shared__ float As[2][8][132];  // [k][m], padded (k-stride 132 avoids STS conflicts)
    __shared__ float Bs[2][8][128];  // [k][n]
    const int tid = threadIdx.x;
    const int tx = tid & 15, ty = tid >> 4;
    const int row0 = blockIdx.x * 128;
    const int a_m = tid >> 1, a_k = (tid & 1) * 4;
    const int b_k = tid >> 5, b_n = (tid & 31) * 4;
    const int arow = row0 + a_m;
    const bool aval = (arow < M);

    float acc[8][8];
#pragma unroll
    for (int i = 0; i < 8; i++)
#pragma unroll
        for (int j = 0; j < 8; j++) acc[i][j] = 0.0f;

    float4 aReg = aval ? *(const float4*)(A + (size_t)arow * 128 + a_k)
                       : make_float4(0.f, 0.f, 0.f, 0.f);
    float4 bReg = *(const float4*)(W + (size_t)b_k * 128 + b_n);
    As[0][a_k + 0][a_m] = aReg.x;
    As[0][a_k + 1][a_m] = aReg.y;
    As[0][a_k + 2][a_m] = aReg.z;
    As[0][a_k + 3][a_m] = aReg.w;
    *(float4*)&Bs[0][b_k][b_n] = bReg;
    __syncthreads();

#pragma unroll 1
    for (int t = 0; t < 16; t++) {
        int cur = t & 1, nxt = cur ^ 1;
        if (t < 15) {
            int k0 = (t + 1) * 8;
            aReg = aval ? *(const float4*)(A + (size_t)arow * 128 + k0 + a_k)
                        : make_float4(0.f, 0.f, 0.f, 0.f);
            bReg = *(const float4*)(W + (size_t)(k0 + b_k) * 128 + b_n);
        }
#pragma unroll
        for (int kk = 0; kk < 8; kk++) {
            float a[8], b[8];
            *(float4*)&a[0] = *(const float4*)&As[cur][kk][ty * 8];
            *(float4*)&a[4] = *(const float4*)&As[cur][kk][ty * 8 + 4];
            *(float4*)&b[0] = *(const float4*)&Bs[cur][kk][tx * 8];
            *(float4*)&b[4] = *(const float4*)&Bs[cur][kk][tx * 8 + 4];
#pragma unroll
            for (int i = 0; i < 8; i++)
#pragma unroll
                for (int j = 0; j < 8; j++) acc[i][j] += a[i] * b[j];
        }
        if (t < 15) {
            As[nxt][a_k + 0][a_m] = aReg.x;
            As[nxt][a_k + 1][a_m] = aReg.y;
            As[nxt][a_k + 2][a_m] = aReg.z;
            As[nxt][a_k + 3][a_m] = aReg.w;
            *(float4*)&Bs[nxt][b_k][b_n] = bReg;
            __syncthreads();
        }
    }

#pragma unroll
    for (int i = 0; i < 8; i++) {
        int r = row0 + ty * 8 + i;
        if (r < M) {
            *(float4*)(C + (size_t)r * 128 + tx * 8) =
                make_float4(acc[i][0], acc[i][1], acc[i][2], acc[i][3]);
            *(float4*)(C + (size_t)r * 128 + tx * 8 + 4) =
                make_float4(acc[i][4], acc[i][5], acc[i][6], acc[i][7]);
        }
    }
}

// ---------------- aggregation: out = relu(A_norm @ XW + bias) ------------
// Warp per node; gather-only via CSR (no float atomics).

__global__ void agg_kernel(const float* __restrict__ XW,
                           const float* __restrict__ B,
                           float* __restrict__ OUT, int n) {
    int gw = (blockIdx.x * blockDim.x + threadIdx.x) >> 5;
    int lane = threadIdx.x & 31;
    if (gw >= n) return;
    float di = g_dinv[gw];
    float w0 = di * di;  // self-loop norm
    float4 a = ((const float4*)(XW + (size_t)gw * 128))[lane];
    float4 acc = make_float4(a.x * w0, a.y * w0, a.z * w0, a.w * w0);
    int p = g_rowStart[gw];
    int pe = g_rowStart[gw + 1];
    // 2x unroll for MLP
    for (; p + 1 < pe; p += 2) {
        int s0 = g_csr_src[p], s1 = g_csr_src[p + 1];
        float n0 = g_csr_norm[p], n1 = g_csr_norm[p + 1];
        float4 v0 = ((const float4*)(XW + (size_t)s0 * 128))[lane];
        float4 v1 = ((const float4*)(XW + (size_t)s1 * 128))[lane];
        acc.x += n0 * v0.x + n1 * v1.x;
        acc.y += n0 * v0.y + n1 * v1.y;
        acc.z += n0 * v0.z + n1 * v1.z;
        acc.w += n0 * v0.w + n1 * v1.w;
    }
    if (p < pe) {
        int s0 = g_csr_src[p];
        float n0 = g_csr_norm[p];
        float4 v0 = ((const float4*)(XW + (size_t)s0 * 128))[lane];
        acc.x += n0 * v0.x;
        acc.y += n0 * v0.y;
        acc.z += n0 * v0.z;
        acc.w += n0 * v0.w;
    }
    float4 b = ((const float4*)B)[lane];
    acc.x = fmaxf(acc.x + b.x, 0.f);
    acc.y = fmaxf(acc.y + b.y, 0.f);
    acc.z = fmaxf(acc.z + b.z, 0.f);
    acc.w = fmaxf(acc.w + b.w, 0.f);
    ((float4*)(OUT + (size_t)gw * 128))[lane] = acc;
}

// ---------------- fused FC head ------------------------------------------
// q = fc2( relu( [h2|action] @ fc1_w + fc1_b ) ) + fc2_b, K = 144.

__global__ __launch_bounds__(256, 2)
void fc_fused_kernel(const float* __restrict__ H, const float* __restrict__ ACT,
                     const float* __restrict__ W, const float* __restrict__ B1,
                     const float* __restrict__ W2, const float* __restrict__ B2,
                     float* __restrict__ out, int M) {
    __shared__ float As[2][8][132];
    __shared__ float Bs[2][8][128];
    __shared__ float red[128][17];
    const int tid = threadIdx.x;
    const int tx = tid & 15, ty = tid >> 4;
    const int row0 = blockIdx.x * 128;
    const int a_m = tid >> 1, a_k = (tid & 1) * 4;
    const int b_k = tid >> 5, b_n = (tid & 31) * 4;
    const int arow = row0 + a_m;
    const bool aval = (arow < M);

    float acc[8][8];
#pragma unroll
    for (int i = 0; i < 8; i++)
#pragma unroll
        for (int j = 0; j < 8; j++) acc[i][j] = 0.0f;

    auto loadA = [&](int k0) -> float4 {
        if (!aval) return make_float4(0.f, 0.f, 0.f, 0.f);
        int k = k0 + a_k;
        if (k < 128) return *(const float4*)(H + (size_t)arow * 128 + k);
        return *(const float4*)(ACT + (size_t)arow * 16 + (k - 128));
    };

    float4 aReg = loadA(0);
    float4 bReg = *(const float4*)(W + (size_t)b_k * 128 + b_n);
    As[0][a_k + 0][a_m] = aReg.x;
    As[0][a_k + 1][a_m] = aReg.y;
    As[0][a_k + 2][a_m] = aReg.z;
    As[0][a_k + 3][a_m] = aReg.w;
    *(float4*)&Bs[0][b_k][b_n] = bReg;
    __syncthreads();

    const int NCH = 18;  // 144 / 8
#pragma unroll 1
    for (int t = 0; t < NCH; t++) {
        int cur = t & 1, nxt = cur ^ 1;
        if (t < NCH - 1) {
            int k0 = (t + 1) * 8;
            aReg = loadA(k0);
            bReg = *(const float4*)(W + (size_t)(k0 + b_k) * 128 + b_n);
        }
#pragma unroll
        for (int kk = 0; kk < 8; kk++) {
            float a[8], b[8];
            *(float4*)&a[0] = *(const float4*)&As[cur][kk][ty * 8];
            *(float4*)&a[4] = *(const float4*)&As[cur][kk][ty * 8 + 4];
            *(float4*)&b[0] = *(const float4*)&Bs[cur][kk][tx * 8];
            *(float4*)&b[4] = *(const float4*)&Bs[cur][kk][tx * 8 + 4];
#pragma unroll
            for (int i = 0; i < 8; i++)
#pragma unroll
                for (int j = 0; j < 8; j++) acc[i][j] += a[i] * b[j];
        }
        if (t < NCH - 1) {
            As[nxt][a_k + 0][a_m] = aReg.x;
            As[nxt][a_k + 1][a_m] = aReg.y;
            As[nxt][a_k + 2][a_m] = aReg.z;
            As[nxt][a_k + 3][a_m] = aReg.w;
            *(float4*)&Bs[nxt][b_k][b_n] = bReg;
            __syncthreads();
        }
    }

    // epilogue: relu(acc + b1) then dot with fc2_w
    float w2[8], b1[8];
#pragma unroll
    for (int j = 0; j < 8; j++) {
        w2[j] = W2[tx * 8 + j];
        b1[j] = B1[tx * 8 + j];
    }
#pragma unroll
    for (int i = 0; i < 8; i++) {
        float p = 0.f;
#pragma unroll
        for (int j = 0; j < 8; j++) {
            float h = fmaxf(acc[i][j] + b1[j], 0.f);
            p += h * w2[j];
        }
        red[ty * 8 + i][tx] = p;
    }
    __syncthreads();
    if (tid < 128) {
        int r = row0 + tid;
        if (r < M) {
            float s = B2[0];
#pragma unroll
            for (int t = 0; t < 16; t++) s += red[tid][t];
            out[r] = s;
        }
    }
}

// ---------------- launch --------------------------------------------------

extern "C" void kernel_launch(void* const* d_in, const int* in_sizes, int n_in,
                              void* d_out, int out_size) {
    const float* x = (const float*)d_in[0];
    const unsigned int* eidx = (const unsigned int*)d_in[1];
    const float* action = (const float*)d_in[2];
    const float* w1 = (const float*)d_in[3];
    const float* b1 = (const float*)d_in[4];
    const float* w2 = (const float*)d_in[5];
    const float* b2 = (const float*)d_in[6];
    const float* fw1 = (const float*)d_in[7];
    const float* fb1 = (const float*)d_in[8];
    const float* fw2 = (const float*)d_in[9];
    const float* fb2 = (const float*)d_in[10];
    float* out = (float*)d_out;

    int n = in_sizes[0] / HD;  // 100000
    int e = in_sizes[1] / 2;   // 1600000

    void *pA = nullptr, *pB = nullptr;
    cudaGetSymbolAddress(&pA, g_bufA);
    cudaGetSymbolAddress(&pB, g_bufB);
    float* bufA = (float*)pA;
    float* bufB = (float*)pB;

    // --- build CSR + normalization (per launch; deterministic work) ---
    zero_kernel<<<(n + 256) / 256, 256>>>(n);
    detect_kernel<<<256, 256>>>(eidx);
    extract_kernel<<<2048, 256>>>(eidx, e);
    dinv_kernel<<<(n + 255) / 256, 256>>>(n);
    scan_kernel<<<1, 1024>>>(n);
    fill_kernel<<<2048, 256>>>(e);

    int gemm_grid = (n + 127) / 128;
    int agg_grid = (n * 32 + 255) / 256;

    // layer 1
    gemm128_kernel<<<gemm_grid, 256>>>(x, w1, bufA, n);
    agg_kernel<<<agg_grid, 256>>>(bufA, b1, bufB, n);
    // layer 2
    gemm128_kernel<<<gemm_grid, 256>>>(bufB, w2, bufA, n);
    agg_kernel<<<agg_grid, 256>>>(bufA, b2, bufB, n);
    // fused FC head
    fc_fused_kernel<<<gemm_grid, 256>>>(bufB, action, fw1, fb1, fw2, fb2, out, n);
}

// round 6
// speedup vs baseline: 1.6322x; 1.6322x over previous
#include <cuda_runtime.h>
#include <cuda_bf16.h>
#include <stdint.h>
#include <math.h>

#define N_MAX 100000
#define E_MAX 1600000
#define HD 128

// ---------------- device scratch (static; no allocations) ----------------
__device__ int   g_src[E_MAX];
__device__ int   g_dst[E_MAX];
__device__ int   g_deg[N_MAX];
__device__ int   g_rowStart[N_MAX + 1];
__device__ int   g_cursor[N_MAX];
__device__ float g_dinv[N_MAX];
__device__ int   g_csr_src[E_MAX];
__device__ float g_csr_norm[E_MAX];
__device__ float g_bufA[(size_t)N_MAX * HD];
__device__ float g_bufB[(size_t)N_MAX * HD];
__device__ int   g_zero_cnt;
__device__ int   g_blk[512];
__device__ int   g_blkoff[512];
// weights pre-converted to bf16 hi/lo, [k][128] row-major
__device__ __nv_bfloat16 g_w1hi[16384], g_w1lo[16384];
__device__ __nv_bfloat16 g_w2hi[16384], g_w2lo[16384];
__device__ __nv_bfloat16 g_fhi[18432],  g_flo[18432];

// ---------------- helpers -------------------------------------------------

__device__ __forceinline__ uint32_t smem_u32(const void* p) {
    uint32_t a;
    asm("{ .reg .u64 t; cvta.to.shared.u64 t, %1; cvt.u32.u64 %0, t; }"
        : "=r"(a) : "l"(p));
    return a;
}

__device__ __forceinline__ void ldsm_x4(uint32_t* r, uint32_t addr) {
    asm volatile("ldmatrix.sync.aligned.m8n8.x4.shared.b16 {%0,%1,%2,%3}, [%4];"
                 : "=r"(r[0]), "=r"(r[1]), "=r"(r[2]), "=r"(r[3]) : "r"(addr));
}

__device__ __forceinline__ void ldsm_x4_t(uint32_t* r, uint32_t addr) {
    asm volatile("ldmatrix.sync.aligned.m8n8.x4.trans.shared.b16 {%0,%1,%2,%3}, [%4];"
                 : "=r"(r[0]), "=r"(r[1]), "=r"(r[2]), "=r"(r[3]) : "r"(addr));
}

__device__ __forceinline__ void mma_bf16(float* c, const uint32_t* a, const uint32_t* b) {
    asm volatile(
        "mma.sync.aligned.m16n8k16.row.col.f32.bf16.bf16.f32 "
        "{%0,%1,%2,%3}, {%4,%5,%6,%7}, {%8,%9}, {%0,%1,%2,%3};"
        : "+f"(c[0]), "+f"(c[1]), "+f"(c[2]), "+f"(c[3])
        : "r"(a[0]), "r"(a[1]), "r"(a[2]), "r"(a[3]), "r"(b[0]), "r"(b[1]));
}

__device__ __forceinline__ uint32_t pack_bf2(__nv_bfloat16 a, __nv_bfloat16 b) {
    __nv_bfloat162 t;
    t.x = a; t.y = b;
    return *reinterpret_cast<uint32_t*>(&t);
}

// split float pair -> (hi pair, lo pair) packed
__device__ __forceinline__ void split2(float x, float y, uint32_t& hi, uint32_t& lo) {
    __nv_bfloat16 hx = __float2bfloat16(x), hy = __float2bfloat16(y);
    __nv_bfloat16 lx = __float2bfloat16(x - __bfloat162float(hx));
    __nv_bfloat16 ly = __float2bfloat16(y - __bfloat162float(hy));
    hi = pack_bf2(hx, hy);
    lo = pack_bf2(lx, ly);
}

// ---------------- preprocessing kernels ----------------

__global__ void zero_kernel(int n) {
    int i = blockIdx.x * blockDim.x + threadIdx.x;
    if (i < n) g_deg[i] = 0;
    if (i == 0) g_zero_cnt = 0;
}

__global__ void detect_kernel(const unsigned int* __restrict__ ebuf) {
    int i = blockIdx.x * blockDim.x + threadIdx.x;  // 65536 threads
    int z = (ebuf[2 * i + 1] == 0u) ? 1 : 0;
    unsigned m = __ballot_sync(0xFFFFFFFFu, z);
    if ((threadIdx.x & 31) == 0) atomicAdd(&g_zero_cnt, __popc(m));
}

__global__ void extract_kernel(const unsigned int* __restrict__ ebuf, int e) {
    bool is64 = (g_zero_cnt > 1000);
    for (int i = blockIdx.x * blockDim.x + threadIdx.x; i < e;
         i += gridDim.x * blockDim.x) {
        int s, d;
        if (is64) {
            s = (int)ebuf[2 * (size_t)i];
            d = (int)ebuf[2 * ((size_t)e + i)];
        } else {
            s = (int)ebuf[i];
            d = (int)ebuf[e + i];
        }
        g_src[i] = s;
        g_dst[i] = d;
        atomicAdd(&g_deg[d], 1);
    }
}

// scan phase 1: per-block (256) partial sums + dinv
__global__ void degscan1_kernel(int n) {
    __shared__ int ws[8];
    int b = blockIdx.x, tid = threadIdx.x, lane = tid & 31, w = tid >> 5;
    int i = b * 256 + tid;
    int v = (i < n) ? g_deg[i] : 0;
    if (i < n) g_dinv[i] = rsqrtf((float)(v + 1));
    int s = v;
#pragma unroll
    for (int o = 16; o; o >>= 1) s += __shfl_down_sync(0xFFFFFFFFu, s, o);
    if (lane == 0) ws[w] = s;
    __syncthreads();
    if (tid == 0) {
        int t = 0;
#pragma unroll
        for (int j = 0; j < 8; j++) t += ws[j];
        g_blk[b] = t;
    }
}

// scan phase 2: exclusive scan of block partials (one block, 512 thr)
__global__ void degscan2_kernel(int nb) {
    __shared__ int ws[16];
    int tid = threadIdx.x, lane = tid & 31, w = tid >> 5;
    int v = (tid < nb) ? g_blk[tid] : 0;
    int incl = v;
#pragma unroll
    for (int o = 1; o < 32; o <<= 1) {
        int t = __shfl_up_sync(0xFFFFFFFFu, incl, o);
        if (lane >= o) incl += t;
    }
    if (lane == 31) ws[w] = incl;
    __syncthreads();
    if (w == 0 && lane < 16) {
        int s = ws[lane];
#pragma unroll
        for (int o = 1; o < 16; o <<= 1) {
            int t = __shfl_up_sync(0xFFFFu, s, o);
            if (lane >= o) s += t;
        }
        ws[lane] = s;
    }
    __syncthreads();
    int excl = (w ? ws[w - 1] : 0) + incl - v;
    if (tid < nb) g_blkoff[tid] = excl;
}

// scan phase 3: local scan + block offset -> rowStart/cursor
__global__ void degscan3_kernel(int n, int e) {
    __shared__ int ws[8];
    int b = blockIdx.x, tid = threadIdx.x, lane = tid & 31, w = tid >> 5;
    int i = b * 256 + tid;
    int v = (i < n) ? g_deg[i] : 0;
    int incl = v;
#pragma unroll
    for (int o = 1; o < 32; o <<= 1) {
        int t = __shfl_up_sync(0xFFFFFFFFu, incl, o);
        if (lane >= o) incl += t;
    }
    if (lane == 31) ws[w] = incl;
    __syncthreads();
    if (w == 0 && lane < 8) {
        int s = ws[lane];
#pragma unroll
        for (int o = 1; o < 8; o <<= 1) {
            int t = __shfl_up_sync(0xFFu, s, o);
            if (lane >= o) s += t;
        }
        ws[lane] = s;
    }
    __syncthreads();
    int excl = g_blkoff[b] + (w ? ws[w - 1] : 0) + incl - v;
    if (i < n) {
        g_rowStart[i] = excl;
        g_cursor[i] = excl;
    }
    if (i == 0) g_rowStart[n] = e;
}

__global__ void fill_kernel(int e) {
    for (int i = blockIdx.x * blockDim.x + threadIdx.x; i < e;
         i += gridDim.x * blockDim.x) {
        int d = g_dst[i];
        int s = g_src[i];
        int pos = atomicAdd(&g_cursor[d], 1);
        g_csr_src[pos] = s;
        g_csr_norm[pos] = g_dinv[s] * g_dinv[d];
    }
}

// ------- weight pre-convert: fp32 -> bf16 hi/lo, [k][128] linear ---------
__global__ void convert_w_kernel(const float* __restrict__ w1,
                                 const float* __restrict__ w2,
                                 const float* __restrict__ fw1) {
    int idx = blockIdx.x * blockDim.x + threadIdx.x;  // 51200
    float val;
    __nv_bfloat16 *hp, *lp;
    int off;
    if (idx < 16384) {
        val = w1[idx]; hp = g_w1hi; lp = g_w1lo; off = idx;
    } else if (idx < 32768) {
        val = w2[idx - 16384]; hp = g_w2hi; lp = g_w2lo; off = idx - 16384;
    } else if (idx < 32768 + 18432) {
        val = fw1[idx - 32768]; hp = g_fhi; lp = g_flo; off = idx - 32768;
    } else {
        return;
    }
    __nv_bfloat16 h = __float2bfloat16(val);
    hp[off] = h;
    lp[off] = __float2bfloat16(val - __bfloat162float(h));
}

// ---------------- split-bf16 warp-MMA GEMM --------------------------------
// C[M,128] = A[M,K] @ W[K,128], D = hiA*hiB + hiA*loB + loA*hiB (fp32 acc).
// 8 warps: 2(M)x4(N); warp tile 64x32; K chunked by 32 through smem.
// FC mode: K=144 (last 16 = action), fused relu(.+b1)@fc2+b2 epilogue.

#define AS_STRIDE 40   // elements; 80B row stride -> conflict-free ldmatrix
#define BS_STRIDE 136  // elements; 272B row stride -> conflict-free ldmatrix

template <bool FC>
__global__ __launch_bounds__(256, 2)
void gemm_mma_kernel(const float* __restrict__ A, const float* __restrict__ ACT,
                     const __nv_bfloat16* __restrict__ Bhi,
                     const __nv_bfloat16* __restrict__ Blo,
                     const float* __restrict__ B1, const float* __restrict__ W2v,
                     const float* __restrict__ B2, float* __restrict__ OUT, int M) {
    __shared__ __align__(16) __nv_bfloat16 sAhi[128 * AS_STRIDE];
    __shared__ __align__(16) __nv_bfloat16 sAlo[128 * AS_STRIDE];
    __shared__ __align__(16) __nv_bfloat16 sBhi[32 * BS_STRIDE];
    __shared__ __align__(16) __nv_bfloat16 sBlo[32 * BS_STRIDE];

    const int tid = threadIdx.x, wid = tid >> 5, lane = tid & 31;
    const int gid = lane >> 2, tg = lane & 3;
    const int wm = wid >> 2, wn = wid & 3;
    const int mbase = wm * 64, nbase = wn * 32;
    const int row0 = blockIdx.x * 128;

    const uint32_t uAhi = smem_u32(sAhi), uAlo = smem_u32(sAlo);
    const uint32_t uBhi = smem_u32(sBhi), uBlo = smem_u32(sBlo);

    float c[4][4][4];
#pragma unroll
    for (int i = 0; i < 4; i++)
#pragma unroll
        for (int j = 0; j < 4; j++)
#pragma unroll
            for (int q = 0; q < 4; q++) c[i][j][q] = 0.0f;

    const int KTOT = FC ? 144 : 128;
    const int srow = tid >> 1;
    const int skb = (tid & 1) * 16;
    const int sarow = row0 + srow;

    for (int k0 = 0; k0 < KTOT; k0 += 32) {
        const int kc = (KTOT - k0 < 32) ? (KTOT - k0) : 32;
        __syncthreads();  // previous iteration's reads done
        // --- stage A: load fp32, split to bf16 hi/lo ---
        if (skb < kc) {
#pragma unroll
            for (int i = 0; i < 4; i++) {
                float4 v = make_float4(0.f, 0.f, 0.f, 0.f);
                int kg = k0 + skb + i * 4;
                if (sarow < M) {
                    if (FC && kg >= 128)
                        v = *(const float4*)(ACT + (size_t)sarow * 16 + (kg - 128));
                    else
                        v = *(const float4*)(A + (size_t)sarow * 128 + kg);
                }
                uint32_t h0, l0, h1, l1;
                split2(v.x, v.y, h0, l0);
                split2(v.z, v.w, h1, l1);
                int si = srow * AS_STRIDE + skb + i * 4;
                *(uint2*)(sAhi + si) = make_uint2(h0, h1);
                *(uint2*)(sAlo + si) = make_uint2(l0, l1);
            }
        }
        // --- stage B: copy pre-converted bf16 rows ---
        for (int idx = tid; idx < kc * 16; idx += 256) {
            int r = idx >> 4, cn = (idx & 15) * 8;
            *(uint4*)(sBhi + r * BS_STRIDE + cn) =
                *(const uint4*)(Bhi + (size_t)(k0 + r) * 128 + cn);
            *(uint4*)(sBlo + r * BS_STRIDE + cn) =
                *(const uint4*)(Blo + (size_t)(k0 + r) * 128 + cn);
        }
        __syncthreads();

        const int nkt = kc >> 4;
        for (int kt = 0; kt < nkt; kt++) {
            const int kk = kt * 16;
            // fragment addresses
            const uint32_t aoff =
                (uint32_t)(((mbase + (lane & 15)) * AS_STRIDE + kk + (lane >> 4) * 8) * 2);
            const uint32_t boff =
                (uint32_t)(((kk + (lane & 15)) * BS_STRIDE + nbase + (lane >> 4) * 8) * 2);

            uint32_t ahi[4][4], b[4][2];
#pragma unroll
            for (int mt = 0; mt < 4; mt++)
                ldsm_x4(ahi[mt], uAhi + aoff + (uint32_t)(mt * 16 * AS_STRIDE * 2));
#pragma unroll
            for (int p = 0; p < 2; p++) {
                uint32_t r4[4];
                ldsm_x4_t(r4, uBhi + boff + (uint32_t)(p * 32));
                b[2 * p][0] = r4[0]; b[2 * p][1] = r4[1];
                b[2 * p + 1][0] = r4[2]; b[2 * p + 1][1] = r4[3];
            }
            // hi * Hi
#pragma unroll
            for (int mt = 0; mt < 4; mt++)
#pragma unroll
                for (int nt = 0; nt < 4; nt++) mma_bf16(c[mt][nt], ahi[mt], b[nt]);
            // lo * Hi
            {
                uint32_t alo[4][4];
#pragma unroll
                for (int mt = 0; mt < 4; mt++)
                    ldsm_x4(alo[mt], uAlo + aoff + (uint32_t)(mt * 16 * AS_STRIDE * 2));
#pragma unroll
                for (int mt = 0; mt < 4; mt++)
#pragma unroll
                    for (int nt = 0; nt < 4; nt++) mma_bf16(c[mt][nt], alo[mt], b[nt]);
            }
            // hi * Lo
#pragma unroll
            for (int p = 0; p < 2; p++) {
                uint32_t r4[4];
                ldsm_x4_t(r4, uBlo + boff + (uint32_t)(p * 32));
                b[2 * p][0] = r4[0]; b[2 * p][1] = r4[1];
                b[2 * p + 1][0] = r4[2]; b[2 * p + 1][1] = r4[3];
            }
#pragma unroll
            for (int mt = 0; mt < 4; mt++)
#pragma unroll
                for (int nt = 0; nt < 4; nt++) mma_bf16(c[mt][nt], ahi[mt], b[nt]);
        }
    }

    // ---------------- epilogue ----------------
    if (!FC) {
#pragma unroll
        for (int mt = 0; mt < 4; mt++) {
            int rlo = row0 + mbase + mt * 16 + gid;
            int rhi = rlo + 8;
#pragma unroll
            for (int nt = 0; nt < 4; nt++) {
                int col = nbase + nt * 8 + tg * 2;
                if (rlo < M)
                    *(float2*)(OUT + (size_t)rlo * 128 + col) =
                        make_float2(c[mt][nt][0], c[mt][nt][1]);
                if (rhi < M)
                    *(float2*)(OUT + (size_t)rhi * 128 + col) =
                        make_float2(c[mt][nt][2], c[mt][nt][3]);
            }
        }
    } else {
        // fused relu(c + b1) . w2 reduction
        float b1v[4][2], w2v[4][2];
#pragma unroll
        for (int nt = 0; nt < 4; nt++) {
            int col = nbase + nt * 8 + tg * 2;
            b1v[nt][0] = B1[col];     b1v[nt][1] = B1[col + 1];
            w2v[nt][0] = W2v[col];    w2v[nt][1] = W2v[col + 1];
        }
        __syncthreads();  // all warps done reading A/B smem before reuse
        float* red = (float*)sAhi;  // [128][4]
#pragma unroll
        for (int mt = 0; mt < 4; mt++) {
            float plo = 0.f, phi = 0.f;
#pragma unroll
            for (int nt = 0; nt < 4; nt++) {
                plo += fmaxf(c[mt][nt][0] + b1v[nt][0], 0.f) * w2v[nt][0]
                     + fmaxf(c[mt][nt][1] + b1v[nt][1], 0.f) * w2v[nt][1];
                phi += fmaxf(c[mt][nt][2] + b1v[nt][0], 0.f) * w2v[nt][0]
                     + fmaxf(c[mt][nt][3] + b1v[nt][1], 0.f) * w2v[nt][1];
            }
            // reduce over the 4 lanes sharing a row (tg = 0..3)
            plo += __shfl_xor_sync(0xFFFFFFFFu, plo, 1);
            plo += __shfl_xor_sync(0xFFFFFFFFu, plo, 2);
            phi += __shfl_xor_sync(0xFFFFFFFFu, phi, 1);
            phi += __shfl_xor_sync(0xFFFFFFFFu, phi, 2);
            if (tg == 0) {
                red[(mbase + mt * 16 + gid) * 4 + wn] = plo;
                red[(mbase + mt * 16 + gid + 8) * 4 + wn] = phi;
            }
        }
        __syncthreads();
        if (tid < 128) {
            int r = row0 + tid;
            if (r < M) {
                OUT[r] = red[tid * 4 + 0] + red[tid * 4 + 1] +
                         red[tid * 4 + 2] + red[tid * 4 + 3] + B2[0];
            }
        }
    }
}

// ---------------- aggregation: out = relu(A_norm @ XW + bias) ------------

__global__ void agg_kernel(const float* __restrict__ XW,
                           const float* __restrict__ B,
                           float* __restrict__ OUT, int n) {
    int gw = (blockIdx.x * blockDim.x + threadIdx.x) >> 5;
    int lane = threadIdx.x & 31;
    if (gw >= n) return;
    float di = g_dinv[gw];
    float w0 = di * di;
    float4 a = ((const float4*)(XW + (size_t)gw * 128))[lane];
    float4 acc = make_float4(a.x * w0, a.y * w0, a.z * w0, a.w * w0);
    int p = g_rowStart[gw];
    int pe = g_rowStart[gw + 1];
    for (; p + 1 < pe; p += 2) {
        int s0 = g_csr_src[p], s1 = g_csr_src[p + 1];
        float n0 = g_csr_norm[p], n1 = g_csr_norm[p + 1];
        float4 v0 = ((const float4*)(XW + (size_t)s0 * 128))[lane];
        float4 v1 = ((const float4*)(XW + (size_t)s1 * 128))[lane];
        acc.x += n0 * v0.x + n1 * v1.x;
        acc.y += n0 * v0.y + n1 * v1.y;
        acc.z += n0 * v0.z + n1 * v1.z;
        acc.w += n0 * v0.w + n1 * v1.w;
    }
    if (p < pe) {
        int s0 = g_csr_src[p];
        float n0 = g_csr_norm[p];
        float4 v0 = ((const float4*)(XW + (size_t)s0 * 128))[lane];
        acc.x += n0 * v0.x;
        acc.y += n0 * v0.y;
        acc.z += n0 * v0.z;
        acc.w += n0 * v0.w;
    }
    float4 b = ((const float4*)B)[lane];
    acc.x = fmaxf(acc.x + b.x, 0.f);
    acc.y = fmaxf(acc.y + b.y, 0.f);
    acc.z = fmaxf(acc.z + b.z, 0.f);
    acc.w = fmaxf(acc.w + b.w, 0.f);
    ((float4*)(OUT + (size_t)gw * 128))[lane] = acc;
}

// ---------------- launch --------------------------------------------------

extern "C" void kernel_launch(void* const* d_in, const int* in_sizes, int n_in,
                              void* d_out, int out_size) {
    const float* x = (const float*)d_in[0];
    const unsigned int* eidx = (const unsigned int*)d_in[1];
    const float* action = (const float*)d_in[2];
    const float* w1 = (const float*)d_in[3];
    const float* b1 = (const float*)d_in[4];
    const float* w2 = (const float*)d_in[5];
    const float* b2 = (const float*)d_in[6];
    const float* fw1 = (const float*)d_in[7];
    const float* fb1 = (const float*)d_in[8];
    const float* fw2 = (const float*)d_in[9];
    const float* fb2 = (const float*)d_in[10];
    float* out = (float*)d_out;

    int n = in_sizes[0] / HD;  // 100000
    int e = in_sizes[1] / 2;   // 1600000

    void *pA = nullptr, *pB = nullptr;
    cudaGetSymbolAddress(&pA, g_bufA);
    cudaGetSymbolAddress(&pB, g_bufB);
    float* bufA = (float*)pA;
    float* bufB = (float*)pB;

    void *p_w1h, *p_w1l, *p_w2h, *p_w2l, *p_fh, *p_fl;
    cudaGetSymbolAddress(&p_w1h, g_w1hi);
    cudaGetSymbolAddress(&p_w1l, g_w1lo);
    cudaGetSymbolAddress(&p_w2h, g_w2hi);
    cudaGetSymbolAddress(&p_w2l, g_w2lo);
    cudaGetSymbolAddress(&p_fh, g_fhi);
    cudaGetSymbolAddress(&p_fl, g_flo);

    int nblk = (n + 255) / 256;  // 391

    // weight pre-convert (independent of edges)
    convert_w_kernel<<<200, 256>>>(w1, w2, fw1);

    // CSR build
    zero_kernel<<<nblk, 256>>>(n);
    detect_kernel<<<256, 256>>>(eidx);
    extract_kernel<<<2048, 256>>>(eidx, e);
    degscan1_kernel<<<nblk, 256>>>(n);
    degscan2_kernel<<<1, 512>>>(nblk);
    degscan3_kernel<<<nblk, 256>>>(n, e);
    fill_kernel<<<2048, 256>>>(e);

    int gemm_grid = (n + 127) / 128;      // 782
    int agg_grid = (n * 32 + 255) / 256;  // 12500

    gemm_mma_kernel<false><<<gemm_grid, 256>>>(
        x, nullptr, (const __nv_bfloat16*)p_w1h, (const __nv_bfloat16*)p_w1l,
        nullptr, nullptr, nullptr, bufA, n);
    agg_kernel<<<agg_grid, 256>>>(bufA, b1, bufB, n);

    gemm_mma_kernel<false><<<gemm_grid, 256>>>(
        bufB, nullptr, (const __nv_bfloat16*)p_w2h, (const __nv_bfloat16*)p_w2l,
        nullptr, nullptr, nullptr, bufA, n);
    agg_kernel<<<agg_grid, 256>>>(bufA, b2, bufB, n);

    gemm_mma_kernel<true><<<gemm_grid, 256>>>(
        bufB, action, (const __nv_bfloat16*)p_fh, (const __nv_bfloat16*)p_fl,
        fb1, fw2, fb2, out, n);
}

// round 8
// speedup vs baseline: 1.9694x; 1.2066x over previous
#include <cuda_runtime.h>
#include <cuda_bf16.h>
#include <cuda_fp16.h>
#include <stdint.h>
#include <math.h>

#define N_MAX 100000
#define E_MAX 1600000
#define HD 128

// ---------------- device scratch (static; no allocations) ----------------
__device__ int   g_src[E_MAX];
__device__ int   g_dst[E_MAX];
__device__ int   g_deg[N_MAX];
__device__ int   g_rowStart[N_MAX + 1];
__device__ int   g_cursor[N_MAX];
__device__ float g_dinv[N_MAX];
__device__ int   g_csr_src[E_MAX];
__device__ float g_csr_norm[E_MAX];
__device__ float g_bufA[(size_t)N_MAX * HD];   // h1 (fp32)
__device__ float g_bufB[(size_t)N_MAX * HD];   // h2 (fp32)
__device__ __half g_bufH[(size_t)N_MAX * HD];  // xw (fp16, per-layer reuse)
__device__ int   g_zero_cnt;
__device__ int   g_blk[512];
__device__ int   g_blkoff[512];
// weights pre-converted to bf16 hi/lo, [k][128] row-major
__device__ __nv_bfloat16 g_w1hi[16384], g_w1lo[16384];
__device__ __nv_bfloat16 g_w2hi[16384], g_w2lo[16384];
__device__ __nv_bfloat16 g_fhi[18432],  g_flo[18432];

// ---------------- helpers -------------------------------------------------

__device__ __forceinline__ uint32_t smem_u32(const void* p) {
    uint32_t a;
    asm("{ .reg .u64 t; cvta.to.shared.u64 t, %1; cvt.u32.u64 %0, t; }"
        : "=r"(a) : "l"(p));
    return a;
}

__device__ __forceinline__ void ldsm_x4(uint32_t* r, uint32_t addr) {
    asm volatile("ldmatrix.sync.aligned.m8n8.x4.shared.b16 {%0,%1,%2,%3}, [%4];"
                 : "=r"(r[0]), "=r"(r[1]), "=r"(r[2]), "=r"(r[3]) : "r"(addr));
}

__device__ __forceinline__ void ldsm_x4_t(uint32_t* r, uint32_t addr) {
    asm volatile("ldmatrix.sync.aligned.m8n8.x4.trans.shared.b16 {%0,%1,%2,%3}, [%4];"
                 : "=r"(r[0]), "=r"(r[1]), "=r"(r[2]), "=r"(r[3]) : "r"(addr));
}

__device__ __forceinline__ void mma_bf16(float* c, const uint32_t* a, const uint32_t* b) {
    asm volatile(
        "mma.sync.aligned.m16n8k16.row.col.f32.bf16.bf16.f32 "
        "{%0,%1,%2,%3}, {%4,%5,%6,%7}, {%8,%9}, {%0,%1,%2,%3};"
        : "+f"(c[0]), "+f"(c[1]), "+f"(c[2]), "+f"(c[3])
        : "r"(a[0]), "r"(a[1]), "r"(a[2]), "r"(a[3]), "r"(b[0]), "r"(b[1]));
}

__device__ __forceinline__ uint32_t pack_bf2(__nv_bfloat16 a, __nv_bfloat16 b) {
    __nv_bfloat162 t;
    t.x = a; t.y = b;
    return *reinterpret_cast<uint32_t*>(&t);
}

__device__ __forceinline__ void split2(float x, float y, uint32_t& hi, uint32_t& lo) {
    __nv_bfloat16 hx = __float2bfloat16(x), hy = __float2bfloat16(y);
    __nv_bfloat16 lx = __float2bfloat16(x - __bfloat162float(hx));
    __nv_bfloat16 ly = __float2bfloat16(y - __bfloat162float(hy));
    hi = pack_bf2(hx, hy);
    lo = pack_bf2(lx, ly);
}

// ---------------- preprocessing kernels ----------------

__global__ void zero_kernel(int n) {
    int i = blockIdx.x * blockDim.x + threadIdx.x;
    if (i < n) g_deg[i] = 0;
    if (i == 0) g_zero_cnt = 0;
}

__global__ void detect_kernel(const unsigned int* __restrict__ ebuf) {
    int i = blockIdx.x * blockDim.x + threadIdx.x;  // 65536 threads
    int z = (ebuf[2 * i + 1] == 0u) ? 1 : 0;
    unsigned m = __ballot_sync(0xFFFFFFFFu, z);
    if ((threadIdx.x & 31) == 0) atomicAdd(&g_zero_cnt, __popc(m));
}

__global__ void extract_kernel(const unsigned int* __restrict__ ebuf, int e) {
    bool is64 = (g_zero_cnt > 1000);
    for (int i = blockIdx.x * blockDim.x + threadIdx.x; i < e;
         i += gridDim.x * blockDim.x) {
        int s, d;
        if (is64) {
            uint2 us = *(const uint2*)(ebuf + 2 * (size_t)i);
            uint2 ud = *(const uint2*)(ebuf + 2 * ((size_t)e + i));
            s = (int)us.x;
            d = (int)ud.x;
        } else {
            s = (int)ebuf[i];
            d = (int)ebuf[e + i];
        }
        g_src[i] = s;
        g_dst[i] = d;
        atomicAdd(&g_deg[d], 1);
    }
}

// scan phase 1: per-block (256) partial sums + dinv
__global__ void degscan1_kernel(int n) {
    __shared__ int ws[8];
    int b = blockIdx.x, tid = threadIdx.x, lane = tid & 31, w = tid >> 5;
    int i = b * 256 + tid;
    int v = (i < n) ? g_deg[i] : 0;
    if (i < n) g_dinv[i] = rsqrtf((float)(v + 1));
    int s = v;
#pragma unroll
    for (int o = 16; o; o >>= 1) s += __shfl_down_sync(0xFFFFFFFFu, s, o);
    if (lane == 0) ws[w] = s;
    __syncthreads();
    if (tid == 0) {
        int t = 0;
#pragma unroll
        for (int j = 0; j < 8; j++) t += ws[j];
        g_blk[b] = t;
    }
}

// scan phase 2: exclusive scan of block partials (one block, 512 thr)
__global__ void degscan2_kernel(int nb) {
    __shared__ int ws[16];
    int tid = threadIdx.x, lane = tid & 31, w = tid >> 5;
    int v = (tid < nb) ? g_blk[tid] : 0;
    int incl = v;
#pragma unroll
    for (int o = 1; o < 32; o <<= 1) {
        int t = __shfl_up_sync(0xFFFFFFFFu, incl, o);
        if (lane >= o) incl += t;
    }
    if (lane == 31) ws[w] = incl;
    __syncthreads();
    if (w == 0 && lane < 16) {
        int s = ws[lane];
#pragma unroll
        for (int o = 1; o < 16; o <<= 1) {
            int t = __shfl_up_sync(0xFFFFu, s, o);
            if (lane >= o) s += t;
        }
        ws[lane] = s;
    }
    __syncthreads();
    int excl = (w ? ws[w - 1] : 0) + incl - v;
    if (tid < nb) g_blkoff[tid] = excl;
}

// scan phase 3: local scan + block offset -> rowStart/cursor
__global__ void degscan3_kernel(int n, int e) {
    __shared__ int ws[8];
    int b = blockIdx.x, tid = threadIdx.x, lane = tid & 31, w = tid >> 5;
    int i = b * 256 + tid;
    int v = (i < n) ? g_deg[i] : 0;
    int incl = v;
#pragma unroll
    for (int o = 1; o < 32; o <<= 1) {
        int t = __shfl_up_sync(0xFFFFFFFFu, incl, o);
        if (lane >= o) incl += t;
    }
    if (lane == 31) ws[w] = incl;
    __syncthreads();
    if (w == 0 && lane < 8) {
        int s = ws[lane];
#pragma unroll
        for (int o = 1; o < 8; o <<= 1) {
            int t = __shfl_up_sync(0xFFu, s, o);
            if (lane >= o) s += t;
        }
        ws[lane] = s;
    }
    __syncthreads();
    int excl = g_blkoff[b] + (w ? ws[w - 1] : 0) + incl - v;
    if (i < n) {
        g_rowStart[i] = excl;
        g_cursor[i] = excl;
    }
    if (i == 0) g_rowStart[n] = e;
}

__global__ void fill_kernel(int e) {
    for (int i = blockIdx.x * blockDim.x + threadIdx.x; i < e;
         i += gridDim.x * blockDim.x) {
        int d = g_dst[i];
        int s = g_src[i];
        int pos = atomicAdd(&g_cursor[d], 1);
        g_csr_src[pos] = s;
        g_csr_norm[pos] = g_dinv[s] * g_dinv[d];
    }
}

// ------- weight pre-convert: fp32 -> bf16 hi/lo, [k][128] linear ---------
__global__ void convert_w_kernel(const float* __restrict__ w1,
                                 const float* __restrict__ w2,
                                 const float* __restrict__ fw1) {
    int idx = blockIdx.x * blockDim.x + threadIdx.x;  // 51200
    float val;
    __nv_bfloat16 *hp, *lp;
    int off;
    if (idx < 16384) {
        val = w1[idx]; hp = g_w1hi; lp = g_w1lo; off = idx;
    } else if (idx < 32768) {
        val = w2[idx - 16384]; hp = g_w2hi; lp = g_w2lo; off = idx - 16384;
    } else if (idx < 32768 + 18432) {
        val = fw1[idx - 32768]; hp = g_fhi; lp = g_flo; off = idx - 32768;
    } else {
        return;
    }
    __nv_bfloat16 h = __float2bfloat16(val);
    hp[off] = h;
    lp[off] = __float2bfloat16(val - __bfloat162float(h));
}

// ---------------- split-bf16 warp-MMA GEMM --------------------------------
// C[M,128] = A[M,K] @ W[K,128], D = hiA*hiB + hiA*loB + loA*hiB (fp32 acc).
// 8 warps: 2(M)x4(N); warp tile 64x32; K chunked by 32 through smem.
// !FC: writes xw as fp16 (halves aggregation gather traffic).
// FC: K=144 (last 16 = action), fused relu(.+b1)@fc2+b2 epilogue, fp32 out.

#define AS_STRIDE 40   // elements; 80B row stride -> conflict-free ldmatrix
#define BS_STRIDE 136  // elements; 272B row stride -> conflict-free ldmatrix

template <bool FC>
__global__ __launch_bounds__(256, 2)
void gemm_mma_kernel(const float* __restrict__ A, const float* __restrict__ ACT,
                     const __nv_bfloat16* __restrict__ Bhi,
                     const __nv_bfloat16* __restrict__ Blo,
                     const float* __restrict__ B1, const float* __restrict__ W2v,
                     const float* __restrict__ B2, void* __restrict__ OUTv, int M) {
    __shared__ __align__(16) __nv_bfloat16 sAhi[128 * AS_STRIDE];
    __shared__ __align__(16) __nv_bfloat16 sAlo[128 * AS_STRIDE];
    __shared__ __align__(16) __nv_bfloat16 sBhi[32 * BS_STRIDE];
    __shared__ __align__(16) __nv_bfloat16 sBlo[32 * BS_STRIDE];

    const int tid = threadIdx.x, wid = tid >> 5, lane = tid & 31;
    const int gid = lane >> 2, tg = lane & 3;
    const int wm = wid >> 2, wn = wid & 3;
    const int mbase = wm * 64, nbase = wn * 32;
    const int row0 = blockIdx.x * 128;

    const uint32_t uAhi = smem_u32(sAhi), uAlo = smem_u32(sAlo);
    const uint32_t uBhi = smem_u32(sBhi), uBlo = smem_u32(sBlo);

    float c[4][4][4];
#pragma unroll
    for (int i = 0; i < 4; i++)
#pragma unroll
        for (int j = 0; j < 4; j++)
#pragma unroll
            for (int q = 0; q < 4; q++) c[i][j][q] = 0.0f;

    const int KTOT = FC ? 144 : 128;
    const int srow = tid >> 1;
    const int skb = (tid & 1) * 16;
    const int sarow = row0 + srow;

    for (int k0 = 0; k0 < KTOT; k0 += 32) {
        const int kc = (KTOT - k0 < 32) ? (KTOT - k0) : 32;
        __syncthreads();  // previous iteration's reads done
        // --- stage A: load fp32, split to bf16 hi/lo ---
        if (skb < kc) {
#pragma unroll
            for (int i = 0; i < 4; i++) {
                float4 v = make_float4(0.f, 0.f, 0.f, 0.f);
                int kg = k0 + skb + i * 4;
                if (sarow < M) {
                    if (FC && kg >= 128)
                        v = *(const float4*)(ACT + (size_t)sarow * 16 + (kg - 128));
                    else
                        v = *(const float4*)(A + (size_t)sarow * 128 + kg);
                }
                uint32_t h0, l0, h1, l1;
                split2(v.x, v.y, h0, l0);
                split2(v.z, v.w, h1, l1);
                int si = srow * AS_STRIDE + skb + i * 4;
                *(uint2*)(sAhi + si) = make_uint2(h0, h1);
                *(uint2*)(sAlo + si) = make_uint2(l0, l1);
            }
        }
        // --- stage B: copy pre-converted bf16 rows ---
        for (int idx = tid; idx < kc * 16; idx += 256) {
            int r = idx >> 4, cn = (idx & 15) * 8;
            *(uint4*)(sBhi + r * BS_STRIDE + cn) =
                *(const uint4*)(Bhi + (size_t)(k0 + r) * 128 + cn);
            *(uint4*)(sBlo + r * BS_STRIDE + cn) =
                *(const uint4*)(Blo + (size_t)(k0 + r) * 128 + cn);
        }
        __syncthreads();

        const int nkt = kc >> 4;
        for (int kt = 0; kt < nkt; kt++) {
            const int kk = kt * 16;
            const uint32_t aoff =
                (uint32_t)(((mbase + (lane & 15)) * AS_STRIDE + kk + (lane >> 4) * 8) * 2);
            const uint32_t boff =
                (uint32_t)(((kk + (lane & 15)) * BS_STRIDE + nbase + (lane >> 4) * 8) * 2);

            uint32_t ahi[4][4], b[4][2];
#pragma unroll
            for (int mt = 0; mt < 4; mt++)
                ldsm_x4(ahi[mt], uAhi + aoff + (uint32_t)(mt * 16 * AS_STRIDE * 2));
#pragma unroll
            for (int p = 0; p < 2; p++) {
                uint32_t r4[4];
                ldsm_x4_t(r4, uBhi + boff + (uint32_t)(p * 32));
                b[2 * p][0] = r4[0]; b[2 * p][1] = r4[1];
                b[2 * p + 1][0] = r4[2]; b[2 * p + 1][1] = r4[3];
            }
            // hi * Hi
#pragma unroll
            for (int mt = 0; mt < 4; mt++)
#pragma unroll
                for (int nt = 0; nt < 4; nt++) mma_bf16(c[mt][nt], ahi[mt], b[nt]);
            // lo * Hi
            {
                uint32_t alo[4][4];
#pragma unroll
                for (int mt = 0; mt < 4; mt++)
                    ldsm_x4(alo[mt], uAlo + aoff + (uint32_t)(mt * 16 * AS_STRIDE * 2));
#pragma unroll
                for (int mt = 0; mt < 4; mt++)
#pragma unroll
                    for (int nt = 0; nt < 4; nt++) mma_bf16(c[mt][nt], alo[mt], b[nt]);
            }
            // hi * Lo
#pragma unroll
            for (int p = 0; p < 2; p++) {
                uint32_t r4[4];
                ldsm_x4_t(r4, uBlo + boff + (uint32_t)(p * 32));
                b[2 * p][0] = r4[0]; b[2 * p][1] = r4[1];
                b[2 * p + 1][0] = r4[2]; b[2 * p + 1][1] = r4[3];
            }
#pragma unroll
            for (int mt = 0; mt < 4; mt++)
#pragma unroll
                for (int nt = 0; nt < 4; nt++) mma_bf16(c[mt][nt], ahi[mt], b[nt]);
        }
    }

    // ---------------- epilogue ----------------
    if (!FC) {
        __half* Oh = (__half*)OUTv;
#pragma unroll
        for (int mt = 0; mt < 4; mt++) {
            int rlo = row0 + mbase + mt * 16 + gid;
            int rhi = rlo + 8;
#pragma unroll
            for (int nt = 0; nt < 4; nt++) {
                int col = nbase + nt * 8 + tg * 2;
                if (rlo < M)
                    *(__half2*)(Oh + (size_t)rlo * 128 + col) =
                        __floats2half2_rn(c[mt][nt][0], c[mt][nt][1]);
                if (rhi < M)
                    *(__half2*)(Oh + (size_t)rhi * 128 + col) =
                        __floats2half2_rn(c[mt][nt][2], c[mt][nt][3]);
            }
        }
    } else {
        float* OUT = (float*)OUTv;
        float b1v[4][2], w2v[4][2];
#pragma unroll
        for (int nt = 0; nt < 4; nt++) {
            int col = nbase + nt * 8 + tg * 2;
            b1v[nt][0] = B1[col];     b1v[nt][1] = B1[col + 1];
            w2v[nt][0] = W2v[col];    w2v[nt][1] = W2v[col + 1];
        }
        __syncthreads();  // all warps done reading A/B smem before reuse
        float* red = (float*)sAhi;  // [128][4]
#pragma unroll
        for (int mt = 0; mt < 4; mt++) {
            float plo = 0.f, phi = 0.f;
#pragma unroll
            for (int nt = 0; nt < 4; nt++) {
                plo += fmaxf(c[mt][nt][0] + b1v[nt][0], 0.f) * w2v[nt][0]
                     + fmaxf(c[mt][nt][1] + b1v[nt][1], 0.f) * w2v[nt][1];
                phi += fmaxf(c[mt][nt][2] + b1v[nt][0], 0.f) * w2v[nt][0]
                     + fmaxf(c[mt][nt][3] + b1v[nt][1], 0.f) * w2v[nt][1];
            }
            plo += __shfl_xor_sync(0xFFFFFFFFu, plo, 1);
            plo += __shfl_xor_sync(0xFFFFFFFFu, plo, 2);
            phi += __shfl_xor_sync(0xFFFFFFFFu, phi, 1);
            phi += __shfl_xor_sync(0xFFFFFFFFu, phi, 2);
            if (tg == 0) {
                red[(mbase + mt * 16 + gid) * 4 + wn] = plo;
                red[(mbase + mt * 16 + gid + 8) * 4 + wn] = phi;
            }
        }
        __syncthreads();
        if (tid < 128) {
            int r = row0 + tid;
            if (r < M) {
                OUT[r] = red[tid * 4 + 0] + red[tid * 4 + 1] +
                         red[tid * 4 + 2] + red[tid * 4 + 3] + B2[0];
            }
        }
    }
}

// ------- aggregation: out = relu(A_norm @ XW + bias), XW in fp16 ---------
// Warp per node; per edge per lane: one 8B load (4 halves), fp32 accumulate.

__global__ void agg_kernel(const __half* __restrict__ XW,
                           const float* __restrict__ B,
                           float* __restrict__ OUT, int n) {
    int gw = (blockIdx.x * blockDim.x + threadIdx.x) >> 5;
    int lane = threadIdx.x & 31;
    if (gw >= n) return;
    float di = g_dinv[gw];
    float w0 = di * di;  // self-loop norm
    uint2 us = ((const uint2*)(XW + (size_t)gw * 128))[lane];
    float2 s0f = __half22float2(*(__half2*)&us.x);
    float2 s1f = __half22float2(*(__half2*)&us.y);
    float4 acc = make_float4(s0f.x * w0, s0f.y * w0, s1f.x * w0, s1f.y * w0);
    int p = g_rowStart[gw];
    int pe = g_rowStart[gw + 1];
    for (; p + 1 < pe; p += 2) {
        int i0 = g_csr_src[p], i1 = g_csr_src[p + 1];
        float n0 = g_csr_norm[p], n1 = g_csr_norm[p + 1];
        uint2 u0 = ((const uint2*)(XW + (size_t)i0 * 128))[lane];
        uint2 u1 = ((const uint2*)(XW + (size_t)i1 * 128))[lane];
        float2 a0 = __half22float2(*(__half2*)&u0.x);
        float2 a1 = __half22float2(*(__half2*)&u0.y);
        float2 b0 = __half22float2(*(__half2*)&u1.x);
        float2 b1 = __half22float2(*(__half2*)&u1.y);
        acc.x += n0 * a0.x + n1 * b0.x;
        acc.y += n0 * a0.y + n1 * b0.y;
        acc.z += n0 * a1.x + n1 * b1.x;
        acc.w += n0 * a1.y + n1 * b1.y;
    }
    if (p < pe) {
        int i0 = g_csr_src[p];
        float n0 = g_csr_norm[p];
        uint2 u0 = ((const uint2*)(XW + (size_t)i0 * 128))[lane];
        float2 a0 = __half22float2(*(__half2*)&u0.x);
        float2 a1 = __half22float2(*(__half2*)&u0.y);
        acc.x += n0 * a0.x;
        acc.y += n0 * a0.y;
        acc.z += n0 * a1.x;
        acc.w += n0 * a1.y;
    }
    float4 b = ((const float4*)B)[lane];
    acc.x = fmaxf(acc.x + b.x, 0.f);
    acc.y = fmaxf(acc.y + b.y, 0.f);
    acc.z = fmaxf(acc.z + b.z, 0.f);
    acc.w = fmaxf(acc.w + b.w, 0.f);
    ((float4*)(OUT + (size_t)gw * 128))[lane] = acc;
}

// ---------------- launch --------------------------------------------------

extern "C" void kernel_launch(void* const* d_in, const int* in_sizes, int n_in,
                              void* d_out, int out_size) {
    const float* x = (const float*)d_in[0];
    const unsigned int* eidx = (const unsigned int*)d_in[1];
    const float* action = (const float*)d_in[2];
    const float* w1 = (const float*)d_in[3];
    const float* b1 = (const float*)d_in[4];
    const float* w2 = (const float*)d_in[5];
    const float* b2 = (const float*)d_in[6];
    const float* fw1 = (const float*)d_in[7];
    const float* fb1 = (const float*)d_in[8];
    const float* fw2 = (const float*)d_in[9];
    const float* fb2 = (const float*)d_in[10];
    float* out = (float*)d_out;

    int n = in_sizes[0] / HD;  // 100000
    int e = in_sizes[1] / 2;   // 1600000

    void *pA = nullptr, *pB = nullptr, *pH = nullptr;
    cudaGetSymbolAddress(&pA, g_bufA);
    cudaGetSymbolAddress(&pB, g_bufB);
    cudaGetSymbolAddress(&pH, g_bufH);
    float* bufA = (float*)pA;
    float* bufB = (float*)pB;
    __half* bufH = (__half*)pH;

    void *p_w1h, *p_w1l, *p_w2h, *p_w2l, *p_fh, *p_fl;
    cudaGetSymbolAddress(&p_w1h, g_w1hi);
    cudaGetSymbolAddress(&p_w1l, g_w1lo);
    cudaGetSymbolAddress(&p_w2h, g_w2hi);
    cudaGetSymbolAddress(&p_w2l, g_w2lo);
    cudaGetSymbolAddress(&p_fh, g_fhi);
    cudaGetSymbolAddress(&p_fl, g_flo);

    int nblk = (n + 255) / 256;  // 391

    // weight pre-convert (independent of edges)
    convert_w_kernel<<<200, 256>>>(w1, w2, fw1);

    // CSR build
    zero_kernel<<<nblk, 256>>>(n);
    detect_kernel<<<256, 256>>>(eidx);
    extract_kernel<<<2048, 256>>>(eidx, e);
    degscan1_kernel<<<nblk, 256>>>(n);
    degscan2_kernel<<<1, 512>>>(nblk);
    degscan3_kernel<<<nblk, 256>>>(n, e);
    fill_kernel<<<2048, 256>>>(e);

    int gemm_grid = (n + 127) / 128;      // 782
    int agg_grid = (n * 32 + 255) / 256;  // 12500

    // layer 1: xw1 (fp16) -> h1 (fp32)
    gemm_mma_kernel<false><<<gemm_grid, 256>>>(
        x, nullptr, (const __nv_bfloat16*)p_w1h, (const __nv_bfloat16*)p_w1l,
        nullptr, nullptr, nullptr, bufH, n);
    agg_kernel<<<agg_grid, 256>>>(bufH, b1, bufA, n);

    // layer 2: xw2 (fp16) -> h2 (fp32)
    gemm_mma_kernel<false><<<gemm_grid, 256>>>(
        bufA, nullptr, (const __nv_bfloat16*)p_w2h, (const __nv_bfloat16*)p_w2l,
        nullptr, nullptr, nullptr, bufH, n);
    agg_kernel<<<agg_grid, 256>>>(bufH, b2, bufB, n);

    // fused FC head
    gemm_mma_kernel<true><<<gemm_grid, 256>>>(
        bufB, action, (const __nv_bfloat16*)p_fh, (const __nv_bfloat16*)p_fl,
        fb1, fw2, fb2, out, n);
}

// round 11
// speedup vs baseline: 2.0756x; 1.0539x over previous
#include <cuda_runtime.h>
#include <cuda_bf16.h>
#include <cuda_fp16.h>
#include <stdint.h>
#include <math.h>

#define N_MAX 100000
#define E_MAX 1600000
#define HD 128

// ---------------- device scratch (static; no allocations) ----------------
__device__ int   g_src[E_MAX];
__device__ int   g_dst[E_MAX];
__device__ int   g_deg[N_MAX];
__device__ int   g_rowStart[N_MAX + 1];
__device__ int   g_cursor[N_MAX];
__device__ float g_dinv[N_MAX];
__device__ int2  g_csr[E_MAX];                 // (src, norm bits) interleaved
__device__ __half g_xw[(size_t)N_MAX * HD];    // xw (fp16)
__device__ __half g_h[(size_t)N_MAX * HD];     // h1/h2 (fp16)
__device__ int   g_blk[512];
__device__ int   g_blkoff[512];
// weights pre-converted to bf16 hi/lo, [k][128] row-major
__device__ __nv_bfloat16 g_w1hi[16384], g_w1lo[16384];
__device__ __nv_bfloat16 g_w2hi[16384], g_w2lo[16384];
__device__ __nv_bfloat16 g_fhi[18432],  g_flo[18432];

// ---------------- helpers -------------------------------------------------

__device__ __forceinline__ uint32_t smem_u32(const void* p) {
    uint32_t a;
    asm("{ .reg .u64 t; cvta.to.shared.u64 t, %1; cvt.u32.u64 %0, t; }"
        : "=r"(a) : "l"(p));
    return a;
}

__device__ __forceinline__ void ldsm_x4(uint32_t* r, uint32_t addr) {
    asm volatile("ldmatrix.sync.aligned.m8n8.x4.shared.b16 {%0,%1,%2,%3}, [%4];"
                 : "=r"(r[0]), "=r"(r[1]), "=r"(r[2]), "=r"(r[3]) : "r"(addr));
}

__device__ __forceinline__ void ldsm_x4_t(uint32_t* r, uint32_t addr) {
    asm volatile("ldmatrix.sync.aligned.m8n8.x4.trans.shared.b16 {%0,%1,%2,%3}, [%4];"
                 : "=r"(r[0]), "=r"(r[1]), "=r"(r[2]), "=r"(r[3]) : "r"(addr));
}

__device__ __forceinline__ void mma_bf16(float* c, const uint32_t* a, const uint32_t* b) {
    asm volatile(
        "mma.sync.aligned.m16n8k16.row.col.f32.bf16.bf16.f32 "
        "{%0,%1,%2,%3}, {%4,%5,%6,%7}, {%8,%9}, {%0,%1,%2,%3};"
        : "+f"(c[0]), "+f"(c[1]), "+f"(c[2]), "+f"(c[3])
        : "r"(a[0]), "r"(a[1]), "r"(a[2]), "r"(a[3]), "r"(b[0]), "r"(b[1]));
}

__device__ __forceinline__ uint32_t pack_bf2(__nv_bfloat16 a, __nv_bfloat16 b) {
    __nv_bfloat162 t;
    t.x = a; t.y = b;
    return *reinterpret_cast<uint32_t*>(&t);
}

__device__ __forceinline__ void split2(float x, float y, uint32_t& hi, uint32_t& lo) {
    __nv_bfloat16 hx = __float2bfloat16(x), hy = __float2bfloat16(y);
    __nv_bfloat16 lx = __float2bfloat16(x - __bfloat162float(hx));
    __nv_bfloat16 ly = __float2bfloat16(y - __bfloat162float(hy));
    hi = pack_bf2(hx, hy);
    lo = pack_bf2(lx, ly);
}

// ---------------- preprocessing kernels ----------------

// prep: zero degrees + weight pre-convert (merged; independent tasks)
__global__ void prep_kernel(int n, const float* __restrict__ w1,
                            const float* __restrict__ w2,
                            const float* __restrict__ fw1) {
    int i = blockIdx.x * blockDim.x + threadIdx.x;
    if (i < n) g_deg[i] = 0;
    // weight convert: 51200 elements
    if (i < 16384) {
        float v = w1[i];
        __nv_bfloat16 h = __float2bfloat16(v);
        g_w1hi[i] = h;
        g_w1lo[i] = __float2bfloat16(v - __bfloat162float(h));
    } else if (i < 32768) {
        int o = i - 16384;
        float v = w2[o];
        __nv_bfloat16 h = __float2bfloat16(v);
        g_w2hi[o] = h;
        g_w2lo[o] = __float2bfloat16(v - __bfloat162float(h));
    } else if (i < 51200) {
        int o = i - 32768;
        float v = fw1[o];
        __nv_bfloat16 h = __float2bfloat16(v);
        g_fhi[o] = h;
        g_flo[o] = __float2bfloat16(v - __bfloat162float(h));
    }
}

// extract src/dst + degree histogram. int64-vs-int32 self-detect:
// warp 0 ballots 32 odd words; int64 (<2^31) -> all high halves zero.
__global__ void extract_kernel(const unsigned int* __restrict__ ebuf, int e) {
    __shared__ int s_is64;
    if (threadIdx.x < 32) {
        int z = (ebuf[2 * threadIdx.x + 1] == 0u) ? 1 : 0;
        unsigned m = __ballot_sync(0xFFFFFFFFu, z);
        if (threadIdx.x == 0) s_is64 = (m == 0xFFFFFFFFu);
    }
    __syncthreads();
    bool is64 = s_is64;
    for (int i = blockIdx.x * blockDim.x + threadIdx.x; i < e;
         i += gridDim.x * blockDim.x) {
        int s, d;
        if (is64) {
            uint2 us = *(const uint2*)(ebuf + 2 * (size_t)i);
            uint2 ud = *(const uint2*)(ebuf + 2 * ((size_t)e + i));
            s = (int)us.x;
            d = (int)ud.x;
        } else {
            s = (int)ebuf[i];
            d = (int)ebuf[e + i];
        }
        g_src[i] = s;
        g_dst[i] = d;
        atomicAdd(&g_deg[d], 1);
    }
}

// scan phase 1: per-block (256) partial sums + dinv
__global__ void degscan1_kernel(int n) {
    __shared__ int ws[8];
    int b = blockIdx.x, tid = threadIdx.x, lane = tid & 31, w = tid >> 5;
    int i = b * 256 + tid;
    int v = (i < n) ? g_deg[i] : 0;
    if (i < n) g_dinv[i] = rsqrtf((float)(v + 1));
    int s = v;
#pragma unroll
    for (int o = 16; o; o >>= 1) s += __shfl_down_sync(0xFFFFFFFFu, s, o);
    if (lane == 0) ws[w] = s;
    __syncthreads();
    if (tid == 0) {
        int t = 0;
#pragma unroll
        for (int j = 0; j < 8; j++) t += ws[j];
        g_blk[b] = t;
    }
}

// scan phase 2: exclusive scan of block partials (one block, 512 thr)
__global__ void degscan2_kernel(int nb) {
    __shared__ int ws[16];
    int tid = threadIdx.x, lane = tid & 31, w = tid >> 5;
    int v = (tid < nb) ? g_blk[tid] : 0;
    int incl = v;
#pragma unroll
    for (int o = 1; o < 32; o <<= 1) {
        int t = __shfl_up_sync(0xFFFFFFFFu, incl, o);
        if (lane >= o) incl += t;
    }
    if (lane == 31) ws[w] = incl;
    __syncthreads();
    if (w == 0 && lane < 16) {
        int s = ws[lane];
#pragma unroll
        for (int o = 1; o < 16; o <<= 1) {
            int t = __shfl_up_sync(0xFFFFu, s, o);
            if (lane >= o) s += t;
        }
        ws[lane] = s;
    }
    __syncthreads();
    int excl = (w ? ws[w - 1] : 0) + incl - v;
    if (tid < nb) g_blkoff[tid] = excl;
}

// scan phase 3: local scan + block offset -> rowStart/cursor
__global__ void degscan3_kernel(int n, int e) {
    __shared__ int ws[8];
    int b = blockIdx.x, tid = threadIdx.x, lane = tid & 31, w = tid >> 5;
    int i = b * 256 + tid;
    int v = (i < n) ? g_deg[i] : 0;
    int incl = v;
#pragma unroll
    for (int o = 1; o < 32; o <<= 1) {
        int t = __shfl_up_sync(0xFFFFFFFFu, incl, o);
        if (lane >= o) incl += t;
    }
    if (lane == 31) ws[w] = incl;
    __syncthreads();
    if (w == 0 && lane < 8) {
        int s = ws[lane];
#pragma unroll
        for (int o = 1; o < 8; o <<= 1) {
            int t = __shfl_up_sync(0xFFu, s, o);
            if (lane >= o) s += t;
        }
        ws[lane] = s;
    }
    __syncthreads();
    int excl = g_blkoff[b] + (w ? ws[w - 1] : 0) + incl - v;
    if (i < n) {
        g_rowStart[i] = excl;
        g_cursor[i] = excl;
    }
    if (i == 0) g_rowStart[n] = e;
}

__global__ void fill_kernel(int e) {
    for (int i = blockIdx.x * blockDim.x + threadIdx.x; i < e;
         i += gridDim.x * blockDim.x) {
        int d = g_dst[i];
        int s = g_src[i];
        int pos = atomicAdd(&g_cursor[d], 1);
        g_csr[pos] = make_int2(s, __float_as_int(g_dinv[s] * g_dinv[d]));
    }
}

// ---------------- split-bf16 warp-MMA GEMM --------------------------------
// C[M,128] = A[M,K] @ W[K,128], D = hiA*hiB + hiA*loB + loA*hiB (fp32 acc).
// AH: A stored fp16 (split is exact). 8 warps: 2(M)x4(N); warp tile 64x32.
// !FC: writes xw fp16. FC: K=144 (last 16 = action fp32), fused head, fp32 out.

#define AS_STRIDE 40   // elements; 80B row stride -> conflict-free ldmatrix
#define BS_STRIDE 136  // elements; 272B row stride -> conflict-free ldmatrix

template <bool AH, bool FC>
__global__ __launch_bounds__(256, 2)
void gemm_mma_kernel(const void* __restrict__ Av, const float* __restrict__ ACT,
                     const __nv_bfloat16* __restrict__ Bhi,
                     const __nv_bfloat16* __restrict__ Blo,
                     const float* __restrict__ B1, const float* __restrict__ W2v,
                     const float* __restrict__ B2, void* __restrict__ OUTv, int M) {
    __shared__ __align__(16) __nv_bfloat16 sAhi[128 * AS_STRIDE];
    __shared__ __align__(16) __nv_bfloat16 sAlo[128 * AS_STRIDE];
    __shared__ __align__(16) __nv_bfloat16 sBhi[32 * BS_STRIDE];
    __shared__ __align__(16) __nv_bfloat16 sBlo[32 * BS_STRIDE];

    const int tid = threadIdx.x, wid = tid >> 5, lane = tid & 31;
    const int gid = lane >> 2, tg = lane & 3;
    const int wm = wid >> 2, wn = wid & 3;
    const int mbase = wm * 64, nbase = wn * 32;
    const int row0 = blockIdx.x * 128;

    const float* Af = (const float*)Av;
    const __half* Ah = (const __half*)Av;

    const uint32_t uAhi = smem_u32(sAhi), uAlo = smem_u32(sAlo);
    const uint32_t uBhi = smem_u32(sBhi), uBlo = smem_u32(sBlo);

    float c[4][4][4];
#pragma unroll
    for (int i = 0; i < 4; i++)
#pragma unroll
        for (int j = 0; j < 4; j++)
#pragma unroll
            for (int q = 0; q < 4; q++) c[i][j][q] = 0.0f;

    const int KTOT = FC ? 144 : 128;
    const int srow = tid >> 1;
    const int skb = (tid & 1) * 16;
    const int sarow = row0 + srow;

    for (int k0 = 0; k0 < KTOT; k0 += 32) {
        const int kc = (KTOT - k0 < 32) ? (KTOT - k0) : 32;
        __syncthreads();  // previous iteration's reads done
        // --- stage A: load, split to bf16 hi/lo ---
        if (skb < kc) {
#pragma unroll
            for (int i = 0; i < 4; i++) {
                float4 v = make_float4(0.f, 0.f, 0.f, 0.f);
                int kg = k0 + skb + i * 4;
                if (sarow < M) {
                    if (FC && kg >= 128) {
                        v = *(const float4*)(ACT + (size_t)sarow * 16 + (kg - 128));
                    } else if (AH) {
                        uint2 u = *(const uint2*)(Ah + (size_t)sarow * 128 + kg);
                        float2 f0 = __half22float2(*(__half2*)&u.x);
                        float2 f1 = __half22float2(*(__half2*)&u.y);
                        v = make_float4(f0.x, f0.y, f1.x, f1.y);
                    } else {
                        v = *(const float4*)(Af + (size_t)sarow * 128 + kg);
                    }
                }
                uint32_t h0, l0, h1, l1;
                split2(v.x, v.y, h0, l0);
                split2(v.z, v.w, h1, l1);
                int si = srow * AS_STRIDE + skb + i * 4;
                *(uint2*)(sAhi + si) = make_uint2(h0, h1);
                *(uint2*)(sAlo + si) = make_uint2(l0, l1);
            }
        }
        // --- stage B: copy pre-converted bf16 rows ---
        for (int idx = tid; idx < kc * 16; idx += 256) {
            int r = idx >> 4, cn = (idx & 15) * 8;
            *(uint4*)(sBhi + r * BS_STRIDE + cn) =
                *(const uint4*)(Bhi + (size_t)(k0 + r) * 128 + cn);
            *(uint4*)(sBlo + r * BS_STRIDE + cn) =
                *(const uint4*)(Blo + (size_t)(k0 + r) * 128 + cn);
        }
        __syncthreads();

        const int nkt = kc >> 4;
        for (int kt = 0; kt < nkt; kt++) {
            const int kk = kt * 16;
            const uint32_t aoff =
                (uint32_t)(((mbase + (lane & 15)) * AS_STRIDE + kk + (lane >> 4) * 8) * 2);
            const uint32_t boff =
                (uint32_t)(((kk + (lane & 15)) * BS_STRIDE + nbase + (lane >> 4) * 8) * 2);

            uint32_t ahi[4][4], b[4][2];
#pragma unroll
            for (int mt = 0; mt < 4; mt++)
                ldsm_x4(ahi[mt], uAhi + aoff + (uint32_t)(mt * 16 * AS_STRIDE * 2));
#pragma unroll
            for (int p = 0; p < 2; p++) {
                uint32_t r4[4];
                ldsm_x4_t(r4, uBhi + boff + (uint32_t)(p * 32));
                b[2 * p][0] = r4[0]; b[2 * p][1] = r4[1];
                b[2 * p + 1][0] = r4[2]; b[2 * p + 1][1] = r4[3];
            }
            // hi * Hi
#pragma unroll
            for (int mt = 0; mt < 4; mt++)
#pragma unroll
                for (int nt = 0; nt < 4; nt++) mma_bf16(c[mt][nt], ahi[mt], b[nt]);
            // lo * Hi
            {
                uint32_t alo[4][4];
#pragma unroll
                for (int mt = 0; mt < 4; mt++)
                    ldsm_x4(alo[mt], uAlo + aoff + (uint32_t)(mt * 16 * AS_STRIDE * 2));
#pragma unroll
                for (int mt = 0; mt < 4; mt++)
#pragma unroll
                    for (int nt = 0; nt < 4; nt++) mma_bf16(c[mt][nt], alo[mt], b[nt]);
            }
            // hi * Lo
#pragma unroll
            for (int p = 0; p < 2; p++) {
                uint32_t r4[4];
                ldsm_x4_t(r4, uBlo + boff + (uint32_t)(p * 32));
                b[2 * p][0] = r4[0]; b[2 * p][1] = r4[1];
                b[2 * p + 1][0] = r4[2]; b[2 * p + 1][1] = r4[3];
            }
#pragma unroll
            for (int mt = 0; mt < 4; mt++)
#pragma unroll
                for (int nt = 0; nt < 4; nt++) mma_bf16(c[mt][nt], ahi[mt], b[nt]);
        }
    }

    // ---------------- epilogue ----------------
    if (!FC) {
        __half* Oh = (__half*)OUTv;
#pragma unroll
        for (int mt = 0; mt < 4; mt++) {
            int rlo = row0 + mbase + mt * 16 + gid;
            int rhi = rlo + 8;
#pragma unroll
            for (int nt = 0; nt < 4; nt++) {
                int col = nbase + nt * 8 + tg * 2;
                if (rlo < M)
                    *(__half2*)(Oh + (size_t)rlo * 128 + col) =
                        __floats2half2_rn(c[mt][nt][0], c[mt][nt][1]);
                if (rhi < M)
                    *(__half2*)(Oh + (size_t)rhi * 128 + col) =
                        __floats2half2_rn(c[mt][nt][2], c[mt][nt][3]);
            }
        }
    } else {
        float* OUT = (float*)OUTv;
        float b1v[4][2], w2v[4][2];
#pragma unroll
        for (int nt = 0; nt < 4; nt++) {
            int col = nbase + nt * 8 + tg * 2;
            b1v[nt][0] = B1[col];     b1v[nt][1] = B1[col + 1];
            w2v[nt][0] = W2v[col];    w2v[nt][1] = W2v[col + 1];
        }
        __syncthreads();  // all warps done reading A/B smem before reuse
        float* red = (float*)sAhi;  // [128][4]
#pragma unroll
        for (int mt = 0; mt < 4; mt++) {
            float plo = 0.f, phi = 0.f;
#pragma unroll
            for (int nt = 0; nt < 4; nt++) {
                plo += fmaxf(c[mt][nt][0] + b1v[nt][0], 0.f) * w2v[nt][0]
                     + fmaxf(c[mt][nt][1] + b1v[nt][1], 0.f) * w2v[nt][1];
                phi += fmaxf(c[mt][nt][2] + b1v[nt][0], 0.f) * w2v[nt][0]
                     + fmaxf(c[mt][nt][3] + b1v[nt][1], 0.f) * w2v[nt][1];
            }
            plo += __shfl_xor_sync(0xFFFFFFFFu, plo, 1);
            plo += __shfl_xor_sync(0xFFFFFFFFu, plo, 2);
            phi += __shfl_xor_sync(0xFFFFFFFFu, phi, 1);
            phi += __shfl_xor_sync(0xFFFFFFFFu, phi, 2);
            if (tg == 0) {
                red[(mbase + mt * 16 + gid) * 4 + wn] = plo;
                red[(mbase + mt * 16 + gid + 8) * 4 + wn] = phi;
            }
        }
        __syncthreads();
        if (tid < 128) {
            int r = row0 + tid;
            if (r < M) {
                OUT[r] = red[tid * 4 + 0] + red[tid * 4 + 1] +
                         red[tid * 4 + 2] + red[tid * 4 + 3] + B2[0];
            }
        }
    }
}

// ------- aggregation: out = relu(A_norm @ XW + bias), fp16 in/out ---------
// Warp per node; interleaved CSR (int2/edge); 4-deep MLP unroll.

__global__ void agg_kernel(const __half* __restrict__ XW,
                           const float* __restrict__ B,
                           __half* __restrict__ OUT, int n) {
    int gw = (blockIdx.x * blockDim.x + threadIdx.x) >> 5;
    int lane = threadIdx.x & 31;
    if (gw >= n) return;
    float di = g_dinv[gw];
    float w0 = di * di;  // self-loop norm
    uint2 us = ((const uint2*)(XW + (size_t)gw * 128))[lane];
    float2 s0f = __half22float2(*(__half2*)&us.x);
    float2 s1f = __half22float2(*(__half2*)&us.y);
    float4 acc = make_float4(s0f.x * w0, s0f.y * w0, s1f.x * w0, s1f.y * w0);
    int p = g_rowStart[gw];
    int pe = g_rowStart[gw + 1];
    for (; p + 3 < pe; p += 4) {
        int2 e0 = g_csr[p],     e1 = g_csr[p + 1];
        int2 e2 = g_csr[p + 2], e3 = g_csr[p + 3];
        uint2 u0 = ((const uint2*)(XW + (size_t)e0.x * 128))[lane];
        uint2 u1 = ((const uint2*)(XW + (size_t)e1.x * 128))[lane];
        uint2 u2 = ((const uint2*)(XW + (size_t)e2.x * 128))[lane];
        uint2 u3 = ((const uint2*)(XW + (size_t)e3.x * 128))[lane];
        float n0 = __int_as_float(e0.y), n1 = __int_as_float(e1.y);
        float n2 = __int_as_float(e2.y), n3 = __int_as_float(e3.y);
        float2 a0 = __half22float2(*(__half2*)&u0.x), a1 = __half22float2(*(__half2*)&u0.y);
        float2 b0 = __half22float2(*(__half2*)&u1.x), b1 = __half22float2(*(__half2*)&u1.y);
        float2 c0 = __half22float2(*(__half2*)&u2.x), c1 = __half22float2(*(__half2*)&u2.y);
        float2 d0 = __half22float2(*(__half2*)&u3.x), d1 = __half22float2(*(__half2*)&u3.y);
        acc.x += n0 * a0.x + n1 * b0.x + n2 * c0.x + n3 * d0.x;
        acc.y += n0 * a0.y + n1 * b0.y + n2 * c0.y + n3 * d0.y;
        acc.z += n0 * a1.x + n1 * b1.x + n2 * c1.x + n3 * d1.x;
        acc.w += n0 * a1.y + n1 * b1.y + n2 * c1.y + n3 * d1.y;
    }
    for (; p < pe; p++) {
        int2 e0 = g_csr[p];
        float n0 = __int_as_float(e0.y);
        uint2 u0 = ((const uint2*)(XW + (size_t)e0.x * 128))[lane];
        float2 a0 = __half22float2(*(__half2*)&u0.x);
        float2 a1 = __half22float2(*(__half2*)&u0.y);
        acc.x += n0 * a0.x;
        acc.y += n0 * a0.y;
        acc.z += n0 * a1.x;
        acc.w += n0 * a1.y;
    }
    float4 b = ((const float4*)B)[lane];
    __half2 o0 = __floats2half2_rn(fmaxf(acc.x + b.x, 0.f), fmaxf(acc.y + b.y, 0.f));
    __half2 o1 = __floats2half2_rn(fmaxf(acc.z + b.z, 0.f), fmaxf(acc.w + b.w, 0.f));
    uint2 ov = make_uint2(*(uint32_t*)&o0, *(uint32_t*)&o1);
    ((uint2*)(OUT + (size_t)gw * 128))[lane] = ov;
}

// ---------------- launch --------------------------------------------------

extern "C" void kernel_launch(void* const* d_in, const int* in_sizes, int n_in,
                              void* d_out, int out_size) {
    const float* x = (const float*)d_in[0];
    const unsigned int* eidx = (const unsigned int*)d_in[1];
    const float* action = (const float*)d_in[2];
    const float* w1 = (const float*)d_in[3];
    const float* b1 = (const float*)d_in[4];
    const float* w2 = (const float*)d_in[5];
    const float* b2 = (const float*)d_in[6];
    const float* fw1 = (const float*)d_in[7];
    const float* fb1 = (const float*)d_in[8];
    const float* fw2 = (const float*)d_in[9];
    const float* fb2 = (const float*)d_in[10];
    float* out = (float*)d_out;

    int n = in_sizes[0] / HD;  // 100000
    int e = in_sizes[1] / 2;   // 1600000

    void *pX = nullptr, *pH = nullptr;
    cudaGetSymbolAddress(&pX, g_xw);
    cudaGetSymbolAddress(&pH, g_h);
    __half* xw = (__half*)pX;
    __half* hbuf = (__half*)pH;

    void *p_w1h, *p_w1l, *p_w2h, *p_w2l, *p_fh, *p_fl;
    cudaGetSymbolAddress(&p_w1h, g_w1hi);
    cudaGetSymbolAddress(&p_w1l, g_w1lo);
    cudaGetSymbolAddress(&p_w2h, g_w2hi);
    cudaGetSymbolAddress(&p_w2l, g_w2lo);
    cudaGetSymbolAddress(&p_fh, g_fhi);
    cudaGetSymbolAddress(&p_fl, g_flo);

    int nblk = (n + 255) / 256;  // 391

    // CSR build + weight convert
    prep_kernel<<<nblk, 256>>>(n, w1, w2, fw1);
    extract_kernel<<<2048, 256>>>(eidx, e);
    degscan1_kernel<<<nblk, 256>>>(n);
    degscan2_kernel<<<1, 512>>>(nblk);
    degscan3_kernel<<<nblk, 256>>>(n, e);
    fill_kernel<<<2048, 256>>>(e);

    int gemm_grid = (n + 127) / 128;      // 782
    int agg_grid = (n * 32 + 255) / 256;  // 12500

    // layer 1: x (fp32) -> xw1 (fp16) -> h1 (fp16)
    gemm_mma_kernel<false, false><<<gemm_grid, 256>>>(
        x, nullptr, (const __nv_bfloat16*)p_w1h, (const __nv_bfloat16*)p_w1l,
        nullptr, nullptr, nullptr, xw, n);
    agg_kernel<<<agg_grid, 256>>>(xw, b1, hbuf, n);

    // layer 2: h1 (fp16) -> xw2 (fp16) -> h2 (fp16)
    gemm_mma_kernel<true, false><<<gemm_grid, 256>>>(
        hbuf, nullptr, (const __nv_bfloat16*)p_w2h, (const __nv_bfloat16*)p_w2l,
        nullptr, nullptr, nullptr, xw, n);
    agg_kernel<<<agg_grid, 256>>>(xw, b2, hbuf, n);

    // fused FC head: h2 (fp16) + action (fp32) -> q (fp32)
    gemm_mma_kernel<true, true><<<gemm_grid, 256>>>(
        hbuf, action, (const __nv_bfloat16*)p_fh, (const __nv_bfloat16*)p_fl,
        fb1, fw2, fb2, out, n);
}

// round 16
// speedup vs baseline: 2.1722x; 1.0465x over previous
#include <cuda_runtime.h>
#include <cuda_bf16.h>
#include <cuda_fp16.h>
#include <stdint.h>
#include <math.h>

#define N_MAX 100000
#define E_MAX 1600000
#define HD 128

// ---------------- device scratch (static; no allocations) ----------------
__device__ int   g_src[E_MAX];
__device__ int   g_dst[E_MAX];
__device__ int   g_deg[N_MAX];
__device__ int   g_rowStart[N_MAX + 1];
__device__ int   g_cursor[N_MAX];
__device__ float g_dinv[N_MAX];
__device__ unsigned g_scanstate[512];          // (state<<30 | sum), unsigned!
__device__ int2  g_csr[E_MAX];                 // (src, dinv_src bits)
__device__ __half g_xw[(size_t)N_MAX * HD];    // xw (fp16)
__device__ __half g_h[(size_t)N_MAX * HD];     // h1/h2 (fp16)
// weights pre-converted to bf16 hi/lo, [k][128] row-major
__device__ __nv_bfloat16 g_w1hi[16384], g_w1lo[16384];
__device__ __nv_bfloat16 g_w2hi[16384], g_w2lo[16384];
__device__ __nv_bfloat16 g_fhi[18432],  g_flo[18432];

// ---------------- helpers -------------------------------------------------

__device__ __forceinline__ uint32_t smem_u32(const void* p) {
    uint32_t a;
    asm("{ .reg .u64 t; cvta.to.shared.u64 t, %1; cvt.u32.u64 %0, t; }"
        : "=r"(a) : "l"(p));
    return a;
}

__device__ __forceinline__ void ldsm_x4(uint32_t* r, uint32_t addr) {
    asm volatile("ldmatrix.sync.aligned.m8n8.x4.shared.b16 {%0,%1,%2,%3}, [%4];"
                 : "=r"(r[0]), "=r"(r[1]), "=r"(r[2]), "=r"(r[3]) : "r"(addr));
}

__device__ __forceinline__ void ldsm_x4_t(uint32_t* r, uint32_t addr) {
    asm volatile("ldmatrix.sync.aligned.m8n8.x4.trans.shared.b16 {%0,%1,%2,%3}, [%4];"
                 : "=r"(r[0]), "=r"(r[1]), "=r"(r[2]), "=r"(r[3]) : "r"(addr));
}

__device__ __forceinline__ void mma_bf16(float* c, const uint32_t* a, const uint32_t* b) {
    asm volatile(
        "mma.sync.aligned.m16n8k16.row.col.f32.bf16.bf16.f32 "
        "{%0,%1,%2,%3}, {%4,%5,%6,%7}, {%8,%9}, {%0,%1,%2,%3};"
        : "+f"(c[0]), "+f"(c[1]), "+f"(c[2]), "+f"(c[3])
        : "r"(a[0]), "r"(a[1]), "r"(a[2]), "r"(a[3]), "r"(b[0]), "r"(b[1]));
}

__device__ __forceinline__ uint32_t pack_bf2(__nv_bfloat16 a, __nv_bfloat16 b) {
    __nv_bfloat162 t;
    t.x = a; t.y = b;
    return *reinterpret_cast<uint32_t*>(&t);
}

__device__ __forceinline__ void split2(float x, float y, uint32_t& hi, uint32_t& lo) {
    __nv_bfloat16 hx = __float2bfloat16(x), hy = __float2bfloat16(y);
    __nv_bfloat16 lx = __float2bfloat16(x - __bfloat162float(hx));
    __nv_bfloat16 ly = __float2bfloat16(y - __bfloat162float(hy));
    hi = pack_bf2(hx, hy);
    lo = pack_bf2(lx, ly);
}

// ---------------- GEMM device body ----------------------------------------
// C[M,128] = A[M,K] @ W[K,128], D = hiA*hiB + hiA*loB + loA*hiB (fp32 acc).
// AH: A fp16 (split exact). !FC: out fp16 xw. FC: K=144, fused head, fp32 out.

#define AS_STRIDE 40   // 80B row stride -> conflict-free ldmatrix
#define BS_STRIDE 136  // 272B row stride -> conflict-free ldmatrix

template <bool AH, bool FC>
__device__ __forceinline__ void gemm_body(
    int bid, const void* __restrict__ Av, const float* __restrict__ ACT,
    const __nv_bfloat16* __restrict__ Bhi, const __nv_bfloat16* __restrict__ Blo,
    const float* __restrict__ B1, const float* __restrict__ W2v,
    const float* __restrict__ B2, void* __restrict__ OUTv, int M,
    __nv_bfloat16* sAhi, __nv_bfloat16* sAlo,
    __nv_bfloat16* sBhi, __nv_bfloat16* sBlo) {

    const int tid = threadIdx.x, wid = tid >> 5, lane = tid & 31;
    const int gid = lane >> 2, tg = lane & 3;
    const int wm = wid >> 2, wn = wid & 3;
    const int mbase = wm * 64, nbase = wn * 32;
    const int row0 = bid * 128;

    const float* Af = (const float*)Av;
    const __half* Ah = (const __half*)Av;

    const uint32_t uAhi = smem_u32(sAhi), uAlo = smem_u32(sAlo);
    const uint32_t uBhi = smem_u32(sBhi), uBlo = smem_u32(sBlo);

    float c[4][4][4];
#pragma unroll
    for (int i = 0; i < 4; i++)
#pragma unroll
        for (int j = 0; j < 4; j++)
#pragma unroll
            for (int q = 0; q < 4; q++) c[i][j][q] = 0.0f;

    const int KTOT = FC ? 144 : 128;
    const int srow = tid >> 1;
    const int skb = (tid & 1) * 16;
    const int sarow = row0 + srow;

    for (int k0 = 0; k0 < KTOT; k0 += 32) {
        const int kc = (KTOT - k0 < 32) ? (KTOT - k0) : 32;
        __syncthreads();
        if (skb < kc) {
#pragma unroll
            for (int i = 0; i < 4; i++) {
                float4 v = make_float4(0.f, 0.f, 0.f, 0.f);
                int kg = k0 + skb + i * 4;
                if (sarow < M) {
                    if (FC && kg >= 128) {
                        v = *(const float4*)(ACT + (size_t)sarow * 16 + (kg - 128));
                    } else if (AH) {
                        uint2 u = *(const uint2*)(Ah + (size_t)sarow * 128 + kg);
                        float2 f0 = __half22float2(*(__half2*)&u.x);
                        float2 f1 = __half22float2(*(__half2*)&u.y);
                        v = make_float4(f0.x, f0.y, f1.x, f1.y);
                    } else {
                        v = *(const float4*)(Af + (size_t)sarow * 128 + kg);
                    }
                }
                uint32_t h0, l0, h1, l1;
                split2(v.x, v.y, h0, l0);
                split2(v.z, v.w, h1, l1);
                int si = srow * AS_STRIDE + skb + i * 4;
                *(uint2*)(sAhi + si) = make_uint2(h0, h1);
                *(uint2*)(sAlo + si) = make_uint2(l0, l1);
            }
        }
        for (int idx = tid; idx < kc * 16; idx += 256) {
            int r = idx >> 4, cn = (idx & 15) * 8;
            *(uint4*)(sBhi + r * BS_STRIDE + cn) =
                *(const uint4*)(Bhi + (size_t)(k0 + r) * 128 + cn);
            *(uint4*)(sBlo + r * BS_STRIDE + cn) =
                *(const uint4*)(Blo + (size_t)(k0 + r) * 128 + cn);
        }
        __syncthreads();

        const int nkt = kc >> 4;
        for (int kt = 0; kt < nkt; kt++) {
            const int kk = kt * 16;
            const uint32_t aoff =
                (uint32_t)(((mbase + (lane & 15)) * AS_STRIDE + kk + (lane >> 4) * 8) * 2);
            const uint32_t boff =
                (uint32_t)(((kk + (lane & 15)) * BS_STRIDE + nbase + (lane >> 4) * 8) * 2);

            uint32_t ahi[4][4], b[4][2];
#pragma unroll
            for (int mt = 0; mt < 4; mt++)
                ldsm_x4(ahi[mt], uAhi + aoff + (uint32_t)(mt * 16 * AS_STRIDE * 2));
#pragma unroll
            for (int p = 0; p < 2; p++) {
                uint32_t r4[4];
                ldsm_x4_t(r4, uBhi + boff + (uint32_t)(p * 32));
                b[2 * p][0] = r4[0]; b[2 * p][1] = r4[1];
                b[2 * p + 1][0] = r4[2]; b[2 * p + 1][1] = r4[3];
            }
#pragma unroll
            for (int mt = 0; mt < 4; mt++)
#pragma unroll
                for (int nt = 0; nt < 4; nt++) mma_bf16(c[mt][nt], ahi[mt], b[nt]);
            {
                uint32_t alo[4][4];
#pragma unroll
                for (int mt = 0; mt < 4; mt++)
                    ldsm_x4(alo[mt], uAlo + aoff + (uint32_t)(mt * 16 * AS_STRIDE * 2));
#pragma unroll
                for (int mt = 0; mt < 4; mt++)
#pragma unroll
                    for (int nt = 0; nt < 4; nt++) mma_bf16(c[mt][nt], alo[mt], b[nt]);
            }
#pragma unroll
            for (int p = 0; p < 2; p++) {
                uint32_t r4[4];
                ldsm_x4_t(r4, uBlo + boff + (uint32_t)(p * 32));
                b[2 * p][0] = r4[0]; b[2 * p][1] = r4[1];
                b[2 * p + 1][0] = r4[2]; b[2 * p + 1][1] = r4[3];
            }
#pragma unroll
            for (int mt = 0; mt < 4; mt++)
#pragma unroll
                for (int nt = 0; nt < 4; nt++) mma_bf16(c[mt][nt], ahi[mt], b[nt]);
        }
    }

    if (!FC) {
        __half* Oh = (__half*)OUTv;
#pragma unroll
        for (int mt = 0; mt < 4; mt++) {
            int rlo = row0 + mbase + mt * 16 + gid;
            int rhi = rlo + 8;
#pragma unroll
            for (int nt = 0; nt < 4; nt++) {
                int col = nbase + nt * 8 + tg * 2;
                if (rlo < M)
                    *(__half2*)(Oh + (size_t)rlo * 128 + col) =
                        __floats2half2_rn(c[mt][nt][0], c[mt][nt][1]);
                if (rhi < M)
                    *(__half2*)(Oh + (size_t)rhi * 128 + col) =
                        __floats2half2_rn(c[mt][nt][2], c[mt][nt][3]);
            }
        }
    } else {
        float* OUT = (float*)OUTv;
        float b1v[4][2], w2v[4][2];
#pragma unroll
        for (int nt = 0; nt < 4; nt++) {
            int col = nbase + nt * 8 + tg * 2;
            b1v[nt][0] = B1[col];     b1v[nt][1] = B1[col + 1];
            w2v[nt][0] = W2v[col];    w2v[nt][1] = W2v[col + 1];
        }
        __syncthreads();
        float* red = (float*)sAhi;  // [128][4]
#pragma unroll
        for (int mt = 0; mt < 4; mt++) {
            float plo = 0.f, phi = 0.f;
#pragma unroll
            for (int nt = 0; nt < 4; nt++) {
                plo += fmaxf(c[mt][nt][0] + b1v[nt][0], 0.f) * w2v[nt][0]
                     + fmaxf(c[mt][nt][1] + b1v[nt][1], 0.f) * w2v[nt][1];
                phi += fmaxf(c[mt][nt][2] + b1v[nt][0], 0.f) * w2v[nt][0]
                     + fmaxf(c[mt][nt][3] + b1v[nt][1], 0.f) * w2v[nt][1];
            }
            plo += __shfl_xor_sync(0xFFFFFFFFu, plo, 1);
            plo += __shfl_xor_sync(0xFFFFFFFFu, plo, 2);
            phi += __shfl_xor_sync(0xFFFFFFFFu, phi, 1);
            phi += __shfl_xor_sync(0xFFFFFFFFu, phi, 2);
            if (tg == 0) {
                red[(mbase + mt * 16 + gid) * 4 + wn] = plo;
                red[(mbase + mt * 16 + gid + 8) * 4 + wn] = phi;
            }
        }
        __syncthreads();
        if (tid < 128) {
            int r = row0 + tid;
            if (r < M) {
                OUT[r] = red[tid * 4 + 0] + red[tid * 4 + 1] +
                         red[tid * 4 + 2] + red[tid * 4 + 3] + B2[0];
            }
        }
    }
}

// ---------------- extract device body -------------------------------------
__device__ __forceinline__ void extract_body(const unsigned int* __restrict__ ebuf,
                                             int e, int blk, int nblk, int* s_is64) {
    if (threadIdx.x < 32) {
        int z = (ebuf[2 * threadIdx.x + 1] == 0u) ? 1 : 0;
        unsigned m = __ballot_sync(0xFFFFFFFFu, z);
        if (threadIdx.x == 0) *s_is64 = (m == 0xFFFFFFFFu);
    }
    __syncthreads();
    bool is64 = *s_is64;
    for (int i = blk * 256 + threadIdx.x; i < e; i += nblk * 256) {
        int s, d;
        if (is64) {
            uint2 us = *(const uint2*)(ebuf + 2 * (size_t)i);
            uint2 ud = *(const uint2*)(ebuf + 2 * ((size_t)e + i));
            s = (int)us.x;
            d = (int)ud.x;
        } else {
            s = (int)ebuf[i];
            d = (int)ebuf[e + i];
        }
        g_src[i] = s;
        g_dst[i] = d;
        atomicAdd(&g_deg[d], 1);
    }
}

// ---------------- kernels --------------------------------------------------

// prep: zero deg + scan flags + weight pre-convert
__global__ void prep_kernel(int n, const float* __restrict__ w1,
                            const float* __restrict__ w2,
                            const float* __restrict__ fw1) {
    int i = blockIdx.x * blockDim.x + threadIdx.x;
    if (i < n) g_deg[i] = 0;
    if (i < 512) g_scanstate[i] = 0u;
    if (i < 16384) {
        float v = w1[i];
        __nv_bfloat16 h = __float2bfloat16(v);
        g_w1hi[i] = h;
        g_w1lo[i] = __float2bfloat16(v - __bfloat162float(h));
    } else if (i < 32768) {
        int o = i - 16384;
        float v = w2[o];
        __nv_bfloat16 h = __float2bfloat16(v);
        g_w2hi[o] = h;
        g_w2lo[o] = __float2bfloat16(v - __bfloat162float(h));
    } else if (i < 51200) {
        int o = i - 32768;
        float v = fw1[o];
        __nv_bfloat16 h = __float2bfloat16(v);
        g_fhi[o] = h;
        g_flo[o] = __float2bfloat16(v - __bfloat162float(h));
    }
}

// phase1: blocks [0,GB) run GEMM1 (x fp32 @ W1 -> xw fp16);
//         blocks [GB, GB+EB) run extract grid-stride.
__global__ __launch_bounds__(256, 2)
void phase1_kernel(const float* __restrict__ x,
                   const __nv_bfloat16* __restrict__ Bhi,
                   const __nv_bfloat16* __restrict__ Blo,
                   __half* __restrict__ xw, int M, int GB,
                   const unsigned int* __restrict__ ebuf, int e, int EB) {
    __shared__ __align__(16) __nv_bfloat16 sAhi[128 * AS_STRIDE];
    __shared__ __align__(16) __nv_bfloat16 sAlo[128 * AS_STRIDE];
    __shared__ __align__(16) __nv_bfloat16 sBhi[32 * BS_STRIDE];
    __shared__ __align__(16) __nv_bfloat16 sBlo[32 * BS_STRIDE];
    __shared__ int s_is64;
    if (blockIdx.x < (unsigned)GB) {
        gemm_body<false, false>(blockIdx.x, x, nullptr, Bhi, Blo,
                                nullptr, nullptr, nullptr, xw, M,
                                sAhi, sAlo, sBhi, sBlo);
    } else {
        extract_body(ebuf, e, blockIdx.x - GB, EB, &s_is64);
    }
}

// fused decoupled-lookback scan: g_deg -> rowStart/cursor, + dinv.
// State word (UNSIGNED): 0 = not ready, 1<<30|agg, 2<<30|inclusive prefix.
__global__ void scan_kernel(int n, int e) {
    __shared__ int ws[8];
    __shared__ int s_prefix;
    const int b = blockIdx.x, tid = threadIdx.x, lane = tid & 31, w = tid >> 5;
    int i = b * 256 + tid;
    int v = (i < n) ? g_deg[i] : 0;
    if (i < n) g_dinv[i] = rsqrtf((float)(v + 1));
    int incl = v;
#pragma unroll
    for (int o = 1; o < 32; o <<= 1) {
        int t = __shfl_up_sync(0xFFFFFFFFu, incl, o);
        if (lane >= o) incl += t;
    }
    if (lane == 31) ws[w] = incl;
    __syncthreads();
    if (w == 0 && lane < 8) {
        int s = ws[lane];
#pragma unroll
        for (int o = 1; o < 8; o <<= 1) {
            int t = __shfl_up_sync(0xFFu, s, o);
            if (lane >= o) s += t;
        }
        ws[lane] = s;
    }
    __syncthreads();
    int blocksum = ws[7];
    if (tid == 0)
        atomicExch((unsigned*)&g_scanstate[b], 0x40000000u | (unsigned)blocksum);
    if (w == 0) {
        int prefix = 0;
        int idx = b - 1;
        while (idx >= 0) {
            int j = idx - lane;
            unsigned s = (j >= 0) ? (unsigned)__ldcg((const int*)&g_scanstate[j])
                                  : 0x80000000u;  // sentinel: prefix 0
            unsigned state = s >> 30;  // unsigned shift: 0 / 1 / 2
            unsigned b2 = __ballot_sync(0xFFFFFFFFu, state == 2u);
            unsigned b0 = __ballot_sync(0xFFFFFFFFu, state == 0u);
            int l2 = b2 ? (__ffs(b2) - 1) : 32;
            int l0 = b0 ? (__ffs(b0) - 1) : 32;
            if (l2 < l0) {
                // lanes [0,l2) aggregates + lane l2 inclusive prefix: done
                int val = (lane <= l2) ? (int)(s & 0x3FFFFFFFu) : 0;
#pragma unroll
                for (int o = 16; o; o >>= 1) val += __shfl_xor_sync(0xFFFFFFFFu, val, o);
                prefix += val;
                break;
            } else {
                // consume lanes [0,l0) aggregates (l0 may be 0 -> re-poll, or 32)
                int val = (lane < l0) ? (int)(s & 0x3FFFFFFFu) : 0;
#pragma unroll
                for (int o = 16; o; o >>= 1) val += __shfl_xor_sync(0xFFFFFFFFu, val, o);
                prefix += val;
                idx -= l0;
            }
        }
        if (lane == 0) {
            atomicExch((unsigned*)&g_scanstate[b],
                       0x80000000u | (unsigned)(prefix + blocksum));
            s_prefix = prefix;
        }
    }
    __syncthreads();
    int excl = s_prefix + (w ? ws[w - 1] : 0) + incl - v;
    if (i < n) {
        g_rowStart[i] = excl;
        g_cursor[i] = excl;
    }
    if (i == 0) g_rowStart[n] = e;
}

__global__ void fill_kernel(int e) {
    for (int i = blockIdx.x * blockDim.x + threadIdx.x; i < e;
         i += gridDim.x * blockDim.x) {
        int d = g_dst[i];
        int s = g_src[i];
        int pos = atomicAdd(&g_cursor[d], 1);
        g_csr[pos] = make_int2(s, __float_as_int(g_dinv[s]));  // dinv_dst folded in agg
    }
}

// standalone GEMM wrappers
template <bool AH, bool FC>
__global__ __launch_bounds__(256, 2)
void gemm_mma_kernel(const void* __restrict__ Av, const float* __restrict__ ACT,
                     const __nv_bfloat16* __restrict__ Bhi,
                     const __nv_bfloat16* __restrict__ Blo,
                     const float* __restrict__ B1, const float* __restrict__ W2v,
                     const float* __restrict__ B2, void* __restrict__ OUTv, int M) {
    __shared__ __align__(16) __nv_bfloat16 sAhi[128 * AS_STRIDE];
    __shared__ __align__(16) __nv_bfloat16 sAlo[128 * AS_STRIDE];
    __shared__ __align__(16) __nv_bfloat16 sBhi[32 * BS_STRIDE];
    __shared__ __align__(16) __nv_bfloat16 sBlo[32 * BS_STRIDE];
    gemm_body<AH, FC>(blockIdx.x, Av, ACT, Bhi, Blo, B1, W2v, B2, OUTv, M,
                      sAhi, sAlo, sBhi, sBlo);
}

// ------- aggregation: h = relu(di*(di*self + sum dinv_s * row) + b) -------
__global__ void agg_kernel(const __half* __restrict__ XW,
                           const float* __restrict__ B,
                           __half* __restrict__ OUT, int n) {
    int gw = (blockIdx.x * blockDim.x + threadIdx.x) >> 5;
    int lane = threadIdx.x & 31;
    if (gw >= n) return;
    float di = g_dinv[gw];
    uint2 us = ((const uint2*)(XW + (size_t)gw * 128))[lane];
    float2 s0f = __half22float2(*(__half2*)&us.x);
    float2 s1f = __half22float2(*(__half2*)&us.y);
    float4 acc = make_float4(s0f.x * di, s0f.y * di, s1f.x * di, s1f.y * di);
    int p = g_rowStart[gw];
    int pe = g_rowStart[gw + 1];
    for (; p + 3 < pe; p += 4) {
        int2 e0 = g_csr[p],     e1 = g_csr[p + 1];
        int2 e2 = g_csr[p + 2], e3 = g_csr[p + 3];
        uint2 u0 = ((const uint2*)(XW + (size_t)e0.x * 128))[lane];
        uint2 u1 = ((const uint2*)(XW + (size_t)e1.x * 128))[lane];
        uint2 u2 = ((const uint2*)(XW + (size_t)e2.x * 128))[lane];
        uint2 u3 = ((const uint2*)(XW + (size_t)e3.x * 128))[lane];
        float n0 = __int_as_float(e0.y), n1 = __int_as_float(e1.y);
        float n2 = __int_as_float(e2.y), n3 = __int_as_float(e3.y);
        float2 a0 = __half22float2(*(__half2*)&u0.x), a1 = __half22float2(*(__half2*)&u0.y);
        float2 b0 = __half22float2(*(__half2*)&u1.x), b1 = __half22float2(*(__half2*)&u1.y);
        float2 c0 = __half22float2(*(__half2*)&u2.x), c1 = __half22float2(*(__half2*)&u2.y);
        float2 d0 = __half22float2(*(__half2*)&u3.x), d1 = __half22float2(*(__half2*)&u3.y);
        acc.x += n0 * a0.x + n1 * b0.x + n2 * c0.x + n3 * d0.x;
        acc.y += n0 * a0.y + n1 * b0.y + n2 * c0.y + n3 * d0.y;
        acc.z += n0 * a1.x + n1 * b1.x + n2 * c1.x + n3 * d1.x;
        acc.w += n0 * a1.y + n1 * b1.y + n2 * c1.y + n3 * d1.y;
    }
    for (; p < pe; p++) {
        int2 e0 = g_csr[p];
        float n0 = __int_as_float(e0.y);
        uint2 u0 = ((const uint2*)(XW + (size_t)e0.x * 128))[lane];
        float2 a0 = __half22float2(*(__half2*)&u0.x);
        float2 a1 = __half22float2(*(__half2*)&u0.y);
        acc.x += n0 * a0.x;
        acc.y += n0 * a0.y;
        acc.z += n0 * a1.x;
        acc.w += n0 * a1.y;
    }
    float4 b = ((const float4*)B)[lane];
    __half2 o0 = __floats2half2_rn(fmaxf(acc.x * di + b.x, 0.f),
                                   fmaxf(acc.y * di + b.y, 0.f));
    __half2 o1 = __floats2half2_rn(fmaxf(acc.z * di + b.z, 0.f),
                                   fmaxf(acc.w * di + b.w, 0.f));
    uint2 ov = make_uint2(*(uint32_t*)&o0, *(uint32_t*)&o1);
    ((uint2*)(OUT + (size_t)gw * 128))[lane] = ov;
}

// ---------------- launch --------------------------------------------------

extern "C" void kernel_launch(void* const* d_in, const int* in_sizes, int n_in,
                              void* d_out, int out_size) {
    const float* x = (const float*)d_in[0];
    const unsigned int* eidx = (const unsigned int*)d_in[1];
    const float* action = (const float*)d_in[2];
    const float* w1 = (const float*)d_in[3];
    const float* b1 = (const float*)d_in[4];
    const float* w2 = (const float*)d_in[5];
    const float* b2 = (const float*)d_in[6];
    const float* fw1 = (const float*)d_in[7];
    const float* fb1 = (const float*)d_in[8];
    const float* fw2 = (const float*)d_in[9];
    const float* fb2 = (const float*)d_in[10];
    float* out = (float*)d_out;

    int n = in_sizes[0] / HD;  // 100000
    int e = in_sizes[1] / 2;   // 1600000

    void *pX = nullptr, *pH = nullptr;
    cudaGetSymbolAddress(&pX, g_xw);
    cudaGetSymbolAddress(&pH, g_h);
    __half* xw = (__half*)pX;
    __half* hbuf = (__half*)pH;

    void *p_w1h, *p_w1l, *p_w2h, *p_w2l, *p_fh, *p_fl;
    cudaGetSymbolAddress(&p_w1h, g_w1hi);
    cudaGetSymbolAddress(&p_w1l, g_w1lo);
    cudaGetSymbolAddress(&p_w2h, g_w2hi);
    cudaGetSymbolAddress(&p_w2l, g_w2lo);
    cudaGetSymbolAddress(&p_fh, g_fhi);
    cudaGetSymbolAddress(&p_fl, g_flo);

    int nblk = (n + 255) / 256;           // 391
    int gemm_grid = (n + 127) / 128;      // 782
    int agg_grid = (n * 32 + 255) / 256;  // 12500
    int EB = 1024;                        // extract blocks inside phase1

    // 1. prep: zero deg/flags + weight convert
    prep_kernel<<<nblk, 256>>>(n, w1, w2, fw1);
    // 2. phase1: GEMM1 and extract concurrently
    phase1_kernel<<<gemm_grid + EB, 256>>>(
        x, (const __nv_bfloat16*)p_w1h, (const __nv_bfloat16*)p_w1l,
        xw, n, gemm_grid, eidx, e, EB);
    // 3. fused scan (deg -> rowStart/cursor, dinv)
    scan_kernel<<<nblk, 256>>>(n, e);
    // 4. CSR fill
    fill_kernel<<<2048, 256>>>(e);
    // 5. layer-1 aggregation
    agg_kernel<<<agg_grid, 256>>>(xw, b1, hbuf, n);
    // 6. GEMM2
    gemm_mma_kernel<true, false><<<gemm_grid, 256>>>(
        hbuf, nullptr, (const __nv_bfloat16*)p_w2h, (const __nv_bfloat16*)p_w2l,
        nullptr, nullptr, nullptr, xw, n);
    // 7. layer-2 aggregation
    agg_kernel<<<agg_grid, 256>>>(xw, b2, hbuf, n);
    // 8. fused FC head
    gemm_mma_kernel<true, true><<<gemm_grid, 256>>>(
        hbuf, action, (const __nv_bfloat16*)p_fh, (const __nv_bfloat16*)p_fl,
        fb1, fw2, fb2, out, n);
}